// round 12
// baseline (speedup 1.0000x reference)
#include <cuda_runtime.h>
#include <cuda_fp16.h>
#include <cstdint>

#define D_MODEL 1024
#define D_FF    4096
#define SEQ     2048
#define BATCH   4
#define NTOK    (BATCH*SEQ)   /* 8192 */
#define NHEAD   16
#define DK      64

// ---------------- scratch (static device globals; no allocation) ----------------
__device__ __half g_xnh  [(size_t)NTOK*D_MODEL];
__device__ __half g_qkvh [(size_t)NTOK*3*D_MODEL];
__device__ __half g_ctxh [(size_t)NTOK*D_MODEL];
__device__ __half g_x1h  [(size_t)NTOK*D_MODEL];
__device__ __half g_ffh  [(size_t)NTOK*D_FF];
__device__ __half g_wqkvh[(size_t)D_MODEL*3*D_MODEL];   // [K=1024][N=3072]
__device__ __half g_woh  [(size_t)D_MODEL*D_MODEL];     // [K][N]
__device__ __half g_w1h  [(size_t)D_MODEL*D_FF];        // [1024][4096]
__device__ __half g_w2h  [(size_t)D_FF*D_MODEL];        // [4096][1024]
__device__ float  g_bqkv [3*D_MODEL];

// ---------------- PTX helpers ----------------
__device__ __forceinline__ uint32_t smem_u32(const void* p) {
    uint32_t a;
    asm("{ .reg .u64 t; cvta.to.shared.u64 t, %1; cvt.u32.u64 %0, t; }"
        : "=r"(a) : "l"(p));
    return a;
}

#define LDSM4(r0, r1, r2, r3, a) \
    asm volatile("ldmatrix.sync.aligned.m8n8.x4.shared.b16 {%0,%1,%2,%3}, [%4];" \
        : "=r"(r0), "=r"(r1), "=r"(r2), "=r"(r3) : "r"(a))
#define LDSM4T(r0, r1, r2, r3, a) \
    asm volatile("ldmatrix.sync.aligned.m8n8.x4.trans.shared.b16 {%0,%1,%2,%3}, [%4];" \
        : "=r"(r0), "=r"(r1), "=r"(r2), "=r"(r3) : "r"(a))

#define CP16(dst, src) \
    asm volatile("cp.async.cg.shared.global [%0], [%1], 16;" :: "r"(dst), "l"(src))
#define CP_COMMIT() asm volatile("cp.async.commit_group;" ::: "memory")
#define CP_WAIT3()  asm volatile("cp.async.wait_group 3;" ::: "memory")
#define CP_WAIT4()  asm volatile("cp.async.wait_group 4;" ::: "memory")

// fp16 MMA, fp32 accum: D(16x8) += A(16x16) @ B(16x8)
__device__ __forceinline__ void mma16(float* d, const uint32_t* a, const uint32_t* b) {
    asm volatile(
        "mma.sync.aligned.m16n8k16.row.col.f32.f16.f16.f32 "
        "{%0,%1,%2,%3}, {%4,%5,%6,%7}, {%8,%9}, {%0,%1,%2,%3};"
        : "+f"(d[0]), "+f"(d[1]), "+f"(d[2]), "+f"(d[3])
        : "r"(a[0]), "r"(a[1]), "r"(a[2]), "r"(a[3]), "r"(b[0]), "r"(b[1]));
}

// ---------------- LayerNorm (f32 in, fp16 out): warp-per-row, MLP=8 ----------------
__global__ void ln_kernel(const float* __restrict__ x,
                          const float* __restrict__ gamma,
                          const float* __restrict__ beta,
                          __half* __restrict__ y)
{
    const int lane = threadIdx.x & 31;
    const int wrp  = threadIdx.x >> 5;
    const int row  = blockIdx.x * 8 + wrp;

    const float4* xr = (const float4*)(x + (size_t)row * D_MODEL);
    float4 v[8];
    #pragma unroll
    for (int i = 0; i < 8; i++) v[i] = xr[lane + 32 * i];

    float s = 0.f, ss = 0.f;
    #pragma unroll
    for (int i = 0; i < 8; i++) {
        s  += v[i].x + v[i].y + v[i].z + v[i].w;
        ss += v[i].x*v[i].x + v[i].y*v[i].y + v[i].z*v[i].z + v[i].w*v[i].w;
    }
    #pragma unroll
    for (int off = 16; off; off >>= 1) {
        s  += __shfl_xor_sync(0xffffffffu, s,  off);
        ss += __shfl_xor_sync(0xffffffffu, ss, off);
    }
    const float mu   = s * (1.0f / D_MODEL);
    const float var  = ss * (1.0f / D_MODEL) - mu * mu;
    const float rstd = rsqrtf(var + 1e-5f);

    __half* yr = y + (size_t)row * D_MODEL;
    #pragma unroll
    for (int i = 0; i < 8; i++) {
        const int e = lane + 32 * i;
        const float4 g4 = ((const float4*)gamma)[e];
        const float4 b4 = ((const float4*)beta)[e];
        const float ox = (v[i].x - mu) * rstd * g4.x + b4.x;
        const float oy = (v[i].y - mu) * rstd * g4.y + b4.y;
        const float oz = (v[i].z - mu) * rstd * g4.z + b4.z;
        const float ow = (v[i].w - mu) * rstd * g4.w + b4.w;
        __half2 h0 = __floats2half2_rn(ox, oy);
        __half2 h1 = __floats2half2_rn(oz, ow);
        uint2 o; o.x = *(uint32_t*)&h0; o.y = *(uint32_t*)&h1;
        *(uint2*)(yr + e * 4) = o;
    }
}

// ---------------- LayerNorm (fp16 in, fp16 out): warp-per-row ----------------
__global__ void ln_kernel_h(const __half* __restrict__ x,
                            const float* __restrict__ gamma,
                            const float* __restrict__ beta,
                            __half* __restrict__ y)
{
    const int lane = threadIdx.x & 31;
    const int wrp  = threadIdx.x >> 5;
    const int row  = blockIdx.x * 8 + wrp;

    const uint4* xr = (const uint4*)(x + (size_t)row * D_MODEL);
    uint4 v[4];
    #pragma unroll
    for (int i = 0; i < 4; i++) v[i] = xr[lane + 32 * i];

    float f[4][8];
    float s = 0.f, ss = 0.f;
    #pragma unroll
    for (int i = 0; i < 4; i++) {
        const uint32_t* u = (const uint32_t*)&v[i];
        #pragma unroll
        for (int j = 0; j < 4; j++) {
            const float2 p = __half22float2(*(const __half2*)&u[j]);
            f[i][2*j]   = p.x;
            f[i][2*j+1] = p.y;
            s  += p.x + p.y;
            ss += p.x*p.x + p.y*p.y;
        }
    }
    #pragma unroll
    for (int off = 16; off; off >>= 1) {
        s  += __shfl_xor_sync(0xffffffffu, s,  off);
        ss += __shfl_xor_sync(0xffffffffu, ss, off);
    }
    const float mu   = s * (1.0f / D_MODEL);
    const float var  = ss * (1.0f / D_MODEL) - mu * mu;
    const float rstd = rsqrtf(var + 1e-5f);

    __half* yr = y + (size_t)row * D_MODEL;
    #pragma unroll
    for (int i = 0; i < 4; i++) {
        const int e = lane + 32 * i;          // 8-half chunk index
        uint4 o;
        uint32_t* ou = (uint32_t*)&o;
        #pragma unroll
        for (int j = 0; j < 4; j++) {
            const float2 g2 = ((const float2*)gamma)[e * 4 + j];
            const float2 b2 = ((const float2*)beta)[e * 4 + j];
            const float ox = (f[i][2*j]   - mu) * rstd * g2.x + b2.x;
            const float oy = (f[i][2*j+1] - mu) * rstd * g2.y + b2.y;
            __half2 h = __floats2half2_rn(ox, oy);
            ou[j] = *(uint32_t*)&h;
        }
        *(uint4*)(yr + e * 8) = o;
    }
}

// ---------------- weight convert: f32 -> f16, 8 float4/thread (MLP=8) ----------------
__global__ void convert_h(const float* __restrict__ in, __half* __restrict__ out)
{
    const size_t b0 = (size_t)blockIdx.x * 8192 + threadIdx.x * 4;
    float4 v[8];
    #pragma unroll
    for (int j = 0; j < 8; j++) v[j] = *(const float4*)(in + b0 + j * 1024);
    #pragma unroll
    for (int j = 0; j < 8; j++) {
        __half2 a = __floats2half2_rn(v[j].x, v[j].y);
        __half2 b = __floats2half2_rn(v[j].z, v[j].w);
        uint2 o; o.x = *(uint32_t*)&a; o.y = *(uint32_t*)&b;
        *(uint2*)(out + b0 + j * 1024) = o;
    }
}

// qkv merge-convert + bias concat
__global__ void convert_qkv(const float* __restrict__ Wq, const float* __restrict__ Wk,
                            const float* __restrict__ Wv, float* __restrict__ bqkv,
                            const float* __restrict__ bq, const float* __restrict__ bk,
                            const float* __restrict__ bv, __half* __restrict__ out)
{
    const int k0 = blockIdx.x * 2;            // grid 512
    const int c  = threadIdx.x;               // 0..255
    const float* srcs[3] = { Wq, Wk, Wv };
    float4 v[2][3];
    #pragma unroll
    for (int r = 0; r < 2; r++)
        #pragma unroll
        for (int j = 0; j < 3; j++)
            v[r][j] = ((const float4*)(srcs[j] + (size_t)(k0 + r) * D_MODEL))[c];
    #pragma unroll
    for (int r = 0; r < 2; r++)
        #pragma unroll
        for (int j = 0; j < 3; j++) {
            __half2 a = __floats2half2_rn(v[r][j].x, v[r][j].y);
            __half2 b = __floats2half2_rn(v[r][j].z, v[r][j].w);
            uint2 o; o.x = *(uint32_t*)&a; o.y = *(uint32_t*)&b;
            *(uint2*)(out + (size_t)(k0 + r) * 3 * D_MODEL + j * D_MODEL + c * 4) = o;
        }
    if (blockIdx.x < 3) {
        const float* src = (blockIdx.x == 0) ? bq : (blockIdx.x == 1) ? bk : bv;
        #pragma unroll
        for (int j = 0; j < 4; j++)
            bqkv[blockIdx.x * 1024 + threadIdx.x + j * 256] = src[threadIdx.x + j * 256];
    }
}

// ---------------- fp16 tensor-core GEMM, 2 CTAs/SM, 6-stage k32 pipeline ----------------
// RES: 0=none, 1=f32 residual (Rf), 2=f16 residual (Rh)
#define STG_BYTES 16384
#define GSM_TOTAL (6 * STG_BYTES)     /* 98304 */

template<bool RELU, int RES, bool HOUT>
__global__ __launch_bounds__(128, 2)
void gemm_h(const __half* __restrict__ Ah, const __half* __restrict__ Bh,
            const float* __restrict__ bias,
            const float* __restrict__ Rf, const __half* __restrict__ Rh,
            float* __restrict__ Cf, __half* __restrict__ Ch, int M, int N, int K)
{
    extern __shared__ char smem[];
    const uint32_t sb = smem_u32(smem);
    const int tid  = threadIdx.x;        // 0..127
    const int lane = tid & 31;
    const int wid  = tid >> 5;           // 0..3
    const int wm   = wid & 1;
    const int wn   = wid >> 1;           // 0..1

    const int m0 = blockIdx.y << 7;
    const int n0 = blockIdx.x << 7;

    const int rlA = lane & 15, clA = lane >> 4;
    const int kV = (lane & 7) + ((lane & 8) ? 8 : 0);
    const int cV = (lane >> 4) & 1;

    float acc[4][8][4];
    #pragma unroll
    for (int mi = 0; mi < 4; mi++)
        #pragma unroll
        for (int ni = 0; ni < 8; ni++)
            #pragma unroll
            for (int c = 0; c < 4; c++) acc[mi][ni][c] = 0.f;

    const int T = K >> 5;

    #define ISSUE_STAGE(s, buf) do { \
        const uint32_t b0_ = sb + (buf) * STG_BYTES; \
        _Pragma("unroll") \
        for (int j = 0; j < 4; j++) { \
            const int c_ = tid + j * 128, row_ = c_ >> 2, ch_ = c_ & 3; \
            CP16(b0_ + row_ * 64 + ((ch_ ^ ((row_ >> 1) & 3)) << 4), \
                 Ah + (size_t)(m0 + row_) * K + (s) * 32 + ch_ * 8); \
        } \
        _Pragma("unroll") \
        for (int j = 0; j < 4; j++) { \
            const int c_ = tid + j * 128, row_ = c_ >> 4, ch_ = c_ & 15; \
            const int ph_ = (ch_ & 8) | ((ch_ & 7) ^ (row_ & 7)); \
            CP16(b0_ + 8192 + row_ * 256 + (ph_ << 4), \
                 Bh + (size_t)((s) * 32 + row_) * N + n0 + ch_ * 8); \
        } \
    } while (0)

    #define LOAD_FRAGS(a_, b_, s_) do { \
        _Pragma("unroll") \
        for (int mi = 0; mi < 4; mi++) { \
            const int row = wm * 64 + mi * 16 + rlA; \
            LDSM4((a_)[mi][0], (a_)[mi][1], (a_)[mi][2], (a_)[mi][3], \
                  sA + row * 64 + (((2 * (s_) + clA) ^ ((row >> 1) & 3)) << 4)); \
        } \
        _Pragma("unroll") \
        for (int bb = 0; bb < 4; bb++) { \
            const int c = wn * 8 + 2 * bb + cV; \
            const int ph = (c & 8) | ((c & 7) ^ (kV & 7)); \
            LDSM4T((b_)[2*bb][0], (b_)[2*bb][1], (b_)[2*bb+1][0], (b_)[2*bb+1][1], \
                   sB + (16 * (s_) + kV) * 256 + (ph << 4)); \
        } \
    } while (0)

    #pragma unroll
    for (int i = 0; i < 5; i++) {
        if (i < T) ISSUE_STAGE(i, i);
        CP_COMMIT();
    }

    uint32_t af[2][4][4], bf[2][8][2];

    int cur = 0;
    for (int kt = 0; kt < T; kt++) {
        CP_WAIT4();
        __syncthreads();
        {
            int nb = cur + 5; if (nb >= 6) nb -= 6;
            if (kt + 5 < T) ISSUE_STAGE(kt + 5, nb);
            CP_COMMIT();
        }
        const uint32_t sA = sb + cur * STG_BYTES;
        const uint32_t sB = sA + 8192;

        LOAD_FRAGS(af[0], bf[0], 0);
        LOAD_FRAGS(af[1], bf[1], 1);
        #pragma unroll
        for (int s = 0; s < 2; s++) {
            #pragma unroll
            for (int mi = 0; mi < 4; mi++)
                #pragma unroll
                for (int ni = 0; ni < 8; ni++)
                    mma16(acc[mi][ni], af[s][mi], bf[s][ni]);
        }
        cur = (cur == 5) ? 0 : cur + 1;
    }
    #undef ISSUE_STAGE
    #undef LOAD_FRAGS

    // ---- epilogue ----
    const int g  = lane >> 2;
    const int t2 = lane & 3;
    #pragma unroll
    for (int ni = 0; ni < 8; ni++) {
        const int c = n0 + wn * 64 + ni * 8 + 2 * t2;
        const float2 bi = *(const float2*)&bias[c];
        #pragma unroll
        for (int mi = 0; mi < 4; mi++) {
            const int r0 = m0 + wm * 64 + mi * 16 + g;
            #pragma unroll
            for (int h = 0; h < 2; h++) {
                const int rr = r0 + h * 8;
                float vx = acc[mi][ni][2 * h]     + bi.x;
                float vy = acc[mi][ni][2 * h + 1] + bi.y;
                if (RELU) { vx = fmaxf(vx, 0.f); vy = fmaxf(vy, 0.f); }
                const size_t idx = (size_t)rr * N + c;
                if (RES == 1) {
                    const float2 rs = *(const float2*)&Rf[idx];
                    vx += rs.x; vy += rs.y;
                } else if (RES == 2) {
                    const float2 rs = __half22float2(*(const __half2*)&Rh[idx]);
                    vx += rs.x; vy += rs.y;
                }
                if (HOUT) {
                    __half2 hv = __floats2half2_rn(vx, vy);
                    *(uint32_t*)&Ch[idx] = *(uint32_t*)&hv;
                } else {
                    float2 o; o.x = vx; o.y = vy;
                    *(float2*)&Cf[idx] = o;
                }
            }
        }
    }
}

// ---------------- fp16 flash attention, register-resident P, 2 CTAs/SM, 5-stage KV ----------------
#define ATT_STG  16384
#define ATT_SMEM (16384 + 5 * ATT_STG)   /* 98304 */

__global__ __launch_bounds__(256, 2)
void attn_h(const __half* __restrict__ Qg, const __half* __restrict__ Kg,
            const __half* __restrict__ Vg, __half* __restrict__ O, int ld)
{
    extern __shared__ char smem[];
    const uint32_t sb = smem_u32(smem);
    const int tid  = threadIdx.x;
    const int lane = tid & 31;
    const int wid  = tid >> 5;
    const int g    = lane >> 2;
    const int t    = lane & 3;
    const int swz  = lane & 7;

    const int bh = blockIdx.y;
    const int b  = bh >> 4;
    const int h  = bh & 15;
    const int q0 = blockIdx.x << 7;

    const size_t base  = (size_t)b * SEQ * ld + (size_t)h * DK;
    const size_t obase = (size_t)b * SEQ * D_MODEL + (size_t)h * DK;

    #pragma unroll
    for (int p = 0; p < 4; p++) {
        const int c = tid + p * 256, row = c >> 3, ch = c & 7;
        *(uint4*)(smem + row * 128 + ((ch ^ (row & 7)) << 4)) =
            *(const uint4*)(Qg + base + (size_t)(q0 + row) * ld + ch * 8);
    }
    __syncthreads();

    uint32_t aq[4][4];
    {
        const int rowA = wid * 16 + (lane & 15);
        const int clA  = lane >> 4;
        #pragma unroll
        for (int kb = 0; kb < 4; kb++)
            LDSM4(aq[kb][0], aq[kb][1], aq[kb][2], aq[kb][3],
                  sb + rowA * 128 + (((2 * kb + clA) ^ swz) << 4));
    }

    const int rlB = (lane & 7) + ((lane >> 4) << 3);
    const int clB = (lane >> 3) & 1;
    const int kV  = (lane & 7) + ((lane & 8) ? 8 : 0);
    const int cV  = (lane >> 4) & 1;

    float m0v = -1e30f, m1v = -1e30f, l0 = 0.f, l1 = 0.f;
    float oacc[8][4];
    #pragma unroll
    for (int ni = 0; ni < 8; ni++)
        #pragma unroll
        for (int c = 0; c < 4; c++) oacc[ni][c] = 0.f;

    #define ISSUE_KV(s, buf) do { \
        const uint32_t kb_ = sb + 16384 + (buf) * ATT_STG; \
        _Pragma("unroll") \
        for (int j = 0; j < 2; j++) { \
            const int c_ = tid + j * 256, row_ = c_ >> 3, ch_ = c_ & 7; \
            const uint32_t off_ = row_ * 128 + ((ch_ ^ (row_ & 7)) << 4); \
            const size_t gsrc = base + (size_t)((s) * 64 + row_) * ld + ch_ * 8; \
            CP16(kb_ + off_,        Kg + gsrc); \
            CP16(kb_ + 8192 + off_, Vg + gsrc); \
        } \
    } while (0)

    const int T = SEQ / 64;
    #pragma unroll
    for (int i = 0; i < 4; i++) {
        if (i < T) ISSUE_KV(i, i);
        CP_COMMIT();
    }

    int cur = 0;
    for (int kt = 0; kt < T; kt++) {
        CP_WAIT3();
        __syncthreads();
        {
            int nb = cur + 4; if (nb >= 5) nb -= 5;
            if (kt + 4 < T) ISSUE_KV(kt + 4, nb);
            CP_COMMIT();
        }
        const uint32_t kbuf = sb + 16384 + cur * ATT_STG;
        const uint32_t vbuf = kbuf + 8192;

        float sacc[8][4];
        #pragma unroll
        for (int ni = 0; ni < 8; ni++)
            #pragma unroll
            for (int c = 0; c < 4; c++) sacc[ni][c] = 0.f;

        #pragma unroll
        for (int kb = 0; kb < 4; kb++) {
            uint32_t bf[8][2];
            #pragma unroll
            for (int a = 0; a < 4; a++) {
                const int row = 16 * a + rlB;
                LDSM4(bf[2*a][0], bf[2*a][1], bf[2*a+1][0], bf[2*a+1][1],
                      kbuf + row * 128 + (((2 * kb + clB) ^ swz) << 4));
            }
            #pragma unroll
            for (int ni = 0; ni < 8; ni++)
                mma16(sacc[ni], aq[kb], bf[ni]);
        }

        #pragma unroll
        for (int ni = 0; ni < 8; ni++) {
            sacc[ni][0] *= 0.125f; sacc[ni][1] *= 0.125f;
            sacc[ni][2] *= 0.125f; sacc[ni][3] *= 0.125f;
        }
        float mx0 = -1e30f, mx1 = -1e30f;
        #pragma unroll
        for (int ni = 0; ni < 8; ni++) {
            mx0 = fmaxf(mx0, fmaxf(sacc[ni][0], sacc[ni][1]));
            mx1 = fmaxf(mx1, fmaxf(sacc[ni][2], sacc[ni][3]));
        }
        mx0 = fmaxf(mx0, __shfl_xor_sync(0xffffffffu, mx0, 1));
        mx0 = fmaxf(mx0, __shfl_xor_sync(0xffffffffu, mx0, 2));
        mx1 = fmaxf(mx1, __shfl_xor_sync(0xffffffffu, mx1, 1));
        mx1 = fmaxf(mx1, __shfl_xor_sync(0xffffffffu, mx1, 2));

        const float mn0 = fmaxf(m0v, mx0);
        const float mn1 = fmaxf(m1v, mx1);
        const float al0 = __expf(m0v - mn0);
        const float al1 = __expf(m1v - mn1);
        m0v = mn0; m1v = mn1;

        uint32_t pa[8][2];
        float sum0 = 0.f, sum1 = 0.f;
        #pragma unroll
        for (int ni = 0; ni < 8; ni++) {
            const float p0 = __expf(sacc[ni][0] - mn0);
            const float p1 = __expf(sacc[ni][1] - mn0);
            const float p2 = __expf(sacc[ni][2] - mn1);
            const float p3 = __expf(sacc[ni][3] - mn1);
            sum0 += p0 + p1; sum1 += p2 + p3;
            __half2 h0 = __floats2half2_rn(p0, p1);
            __half2 h1 = __floats2half2_rn(p2, p3);
            pa[ni][0] = *(uint32_t*)&h0;
            pa[ni][1] = *(uint32_t*)&h1;
        }
        sum0 += __shfl_xor_sync(0xffffffffu, sum0, 1);
        sum0 += __shfl_xor_sync(0xffffffffu, sum0, 2);
        sum1 += __shfl_xor_sync(0xffffffffu, sum1, 1);
        sum1 += __shfl_xor_sync(0xffffffffu, sum1, 2);
        l0 = l0 * al0 + sum0;
        l1 = l1 * al1 + sum1;

        #pragma unroll
        for (int ni = 0; ni < 8; ni++) {
            oacc[ni][0] *= al0; oacc[ni][1] *= al0;
            oacc[ni][2] *= al1; oacc[ni][3] *= al1;
        }

        #pragma unroll
        for (int kk = 0; kk < 4; kk++) {
            uint32_t bv[8][2];
            #pragma unroll
            for (int bb = 0; bb < 4; bb++) {
                const int key = 16 * kk + kV;
                LDSM4T(bv[2*bb][0], bv[2*bb][1], bv[2*bb+1][0], bv[2*bb+1][1],
                       vbuf + key * 128 + (((2 * bb + cV) ^ swz) << 4));
            }
            uint32_t ap[4] = { pa[2*kk][0], pa[2*kk][1], pa[2*kk+1][0], pa[2*kk+1][1] };
            #pragma unroll
            for (int ni = 0; ni < 8; ni++)
                mma16(oacc[ni], ap, bv[ni]);
        }

        cur = (cur == 4) ? 0 : cur + 1;
    }
    #undef ISSUE_KV

    const float inv0 = 1.f / l0;
    const float inv1 = 1.f / l1;
    const size_t row0 = obase + (size_t)(q0 + wid * 16 + g) * D_MODEL;
    const size_t row1 = row0 + (size_t)8 * D_MODEL;
    #pragma unroll
    for (int ni = 0; ni < 8; ni++) {
        const int c = ni * 8 + 2 * t;
        __half2 h0 = __floats2half2_rn(oacc[ni][0] * inv0, oacc[ni][1] * inv0);
        __half2 h1 = __floats2half2_rn(oacc[ni][2] * inv1, oacc[ni][3] * inv1);
        *(uint32_t*)&O[row0 + c] = *(uint32_t*)&h0;
        *(uint32_t*)&O[row1 + c] = *(uint32_t*)&h1;
    }
}

// ---------------- launch ----------------
extern "C" void kernel_launch(void* const* d_in, const int* in_sizes, int n_in,
                              void* d_out, int out_size)
{
    const float* x    = (const float*)d_in[0];
    const float* ln1g = (const float*)d_in[1];
    const float* ln1b = (const float*)d_in[2];
    const float* ln2g = (const float*)d_in[3];
    const float* ln2b = (const float*)d_in[4];
    const float* Wq = (const float*)d_in[5];
    const float* bq = (const float*)d_in[6];
    const float* Wk = (const float*)d_in[7];
    const float* bk = (const float*)d_in[8];
    const float* Wv = (const float*)d_in[9];
    const float* bv = (const float*)d_in[10];
    const float* Wo = (const float*)d_in[11];
    const float* bo = (const float*)d_in[12];
    const float* W1 = (const float*)d_in[13];
    const float* b1 = (const float*)d_in[14];
    const float* W2 = (const float*)d_in[15];
    const float* b2 = (const float*)d_in[16];
    float* out = (float*)d_out;

    __half *xnh, *qkvh, *ctxh, *x1h, *ffh, *wqkvh, *woh, *w1h, *w2h;
    float *bqkv;
    cudaGetSymbolAddress((void**)&xnh,   g_xnh);
    cudaGetSymbolAddress((void**)&qkvh,  g_qkvh);
    cudaGetSymbolAddress((void**)&ctxh,  g_ctxh);
    cudaGetSymbolAddress((void**)&x1h,   g_x1h);
    cudaGetSymbolAddress((void**)&ffh,   g_ffh);
    cudaGetSymbolAddress((void**)&wqkvh, g_wqkvh);
    cudaGetSymbolAddress((void**)&woh,   g_woh);
    cudaGetSymbolAddress((void**)&w1h,   g_w1h);
    cudaGetSymbolAddress((void**)&w2h,   g_w2h);
    cudaGetSymbolAddress((void**)&bqkv,  g_bqkv);

    cudaFuncSetAttribute(attn_h, cudaFuncAttributeMaxDynamicSharedMemorySize, ATT_SMEM);
    cudaFuncSetAttribute(gemm_h<false,0,true>, cudaFuncAttributeMaxDynamicSharedMemorySize, GSM_TOTAL);
    cudaFuncSetAttribute(gemm_h<false,1,true>, cudaFuncAttributeMaxDynamicSharedMemorySize, GSM_TOTAL);
    cudaFuncSetAttribute(gemm_h<true,0,true>,  cudaFuncAttributeMaxDynamicSharedMemorySize, GSM_TOTAL);
    cudaFuncSetAttribute(gemm_h<false,2,false>,cudaFuncAttributeMaxDynamicSharedMemorySize, GSM_TOTAL);

    // weight converts (f32 -> f16, layout preserved [K,N]) + fused bias concat
    convert_qkv<<<512, 256>>>(Wq, Wk, Wv, bqkv, bq, bk, bv, wqkvh);
    convert_h<<<(D_MODEL*D_MODEL)/8192, 256>>>(Wo, woh);
    convert_h<<<(D_MODEL*D_FF)/8192, 256>>>(W1, w1h);
    convert_h<<<(D_FF*D_MODEL)/8192, 256>>>(W2, w2h);

    // 1) xn = LN1(x)  (fp16 out)
    ln_kernel<<<NTOK/8, 256>>>(x, ln1g, ln1b, xnh);
    // 2) qkv = xn @ [Wq|Wk|Wv] + [bq|bk|bv]   (fused, N=3072, fp16 out)
    gemm_h<false,0,true><<<dim3(3*D_MODEL/128, NTOK/128), 128, GSM_TOTAL>>>(
        xnh, wqkvh, bqkv, nullptr, nullptr, nullptr, qkvh, NTOK, 3*D_MODEL, D_MODEL);
    // 3) ctx = attention(q,k,v)  (fp16 in/out)
    attn_h<<<dim3(SEQ/128, BATCH*NHEAD), 256, ATT_SMEM>>>(
        qkvh, qkvh + D_MODEL, qkvh + 2*D_MODEL, ctxh, 3*D_MODEL);
    // 4) x1 = x + ctx @ Wo + bo  (fp16 out, f32 residual)
    gemm_h<false,1,true><<<dim3(D_MODEL/128, NTOK/128), 128, GSM_TOTAL>>>(
        ctxh, woh, bo, x, nullptr, nullptr, x1h, NTOK, D_MODEL, D_MODEL);
    // 5) xn = LN2(x1)  (fp16 in/out)
    ln_kernel_h<<<NTOK/8, 256>>>(x1h, ln2g, ln2b, xnh);
    // 6) ffh = relu(xn @ W1 + b1)  (fp16 out)
    gemm_h<true,0,true><<<dim3(D_FF/128, NTOK/128), 128, GSM_TOTAL>>>(
        xnh, w1h, b1, nullptr, nullptr, nullptr, ffh, NTOK, D_FF, D_MODEL);
    // 7) out = x1 + ffh @ W2 + b2  (f32 out, fp16 residual)
    gemm_h<false,2,false><<<dim3(D_MODEL/128, NTOK/128), 128, GSM_TOTAL>>>(
        ffh, w2h, b2, nullptr, x1h, out, nullptr, NTOK, D_MODEL, D_FF);
}

// round 13
// speedup vs baseline: 1.0141x; 1.0141x over previous
#include <cuda_runtime.h>
#include <cuda_fp16.h>
#include <cstdint>

#define D_MODEL 1024
#define D_FF    4096
#define SEQ     2048
#define BATCH   4
#define NTOK    (BATCH*SEQ)   /* 8192 */
#define NHEAD   16
#define DK      64

// ---------------- scratch (static device globals; no allocation) ----------------
__device__ __half g_xnh  [(size_t)NTOK*D_MODEL];
__device__ __half g_qkvh [(size_t)NTOK*3*D_MODEL];
__device__ __half g_ctxh [(size_t)NTOK*D_MODEL];
__device__ float  g_x1   [(size_t)NTOK*D_MODEL];
__device__ __half g_ffh  [(size_t)NTOK*D_FF];
__device__ __half g_wqkvh[(size_t)D_MODEL*3*D_MODEL];   // [K=1024][N=3072]
__device__ __half g_woh  [(size_t)D_MODEL*D_MODEL];     // [K][N]
__device__ __half g_w1h  [(size_t)D_MODEL*D_FF];        // [1024][4096]
__device__ __half g_w2h  [(size_t)D_FF*D_MODEL];        // [4096][1024]
__device__ float  g_bqkv [3*D_MODEL];

// ---------------- PTX helpers ----------------
__device__ __forceinline__ uint32_t smem_u32(const void* p) {
    uint32_t a;
    asm("{ .reg .u64 t; cvta.to.shared.u64 t, %1; cvt.u32.u64 %0, t; }"
        : "=r"(a) : "l"(p));
    return a;
}

#define LDSM4(r0, r1, r2, r3, a) \
    asm volatile("ldmatrix.sync.aligned.m8n8.x4.shared.b16 {%0,%1,%2,%3}, [%4];" \
        : "=r"(r0), "=r"(r1), "=r"(r2), "=r"(r3) : "r"(a))
#define LDSM4T(r0, r1, r2, r3, a) \
    asm volatile("ldmatrix.sync.aligned.m8n8.x4.trans.shared.b16 {%0,%1,%2,%3}, [%4];" \
        : "=r"(r0), "=r"(r1), "=r"(r2), "=r"(r3) : "r"(a))

#define CP16(dst, src) \
    asm volatile("cp.async.cg.shared.global [%0], [%1], 16;" :: "r"(dst), "l"(src))
#define CP_COMMIT() asm volatile("cp.async.commit_group;" ::: "memory")
#define CP_WAIT1()  asm volatile("cp.async.wait_group 1;" ::: "memory")
#define CP_WAIT4()  asm volatile("cp.async.wait_group 4;" ::: "memory")

// fp16 MMA, fp32 accum: D(16x8) += A(16x16) @ B(16x8)
__device__ __forceinline__ void mma16(float* d, const uint32_t* a, const uint32_t* b) {
    asm volatile(
        "mma.sync.aligned.m16n8k16.row.col.f32.f16.f16.f32 "
        "{%0,%1,%2,%3}, {%4,%5,%6,%7}, {%8,%9}, {%0,%1,%2,%3};"
        : "+f"(d[0]), "+f"(d[1]), "+f"(d[2]), "+f"(d[3])
        : "r"(a[0]), "r"(a[1]), "r"(a[2]), "r"(a[3]), "r"(b[0]), "r"(b[1]));
}

// ---------------- LayerNorm: warp-per-row, MLP=8, f32 in fp16 out ----------------
__global__ void ln_kernel(const float* __restrict__ x,
                          const float* __restrict__ gamma,
                          const float* __restrict__ beta,
                          __half* __restrict__ y)
{
    const int lane = threadIdx.x & 31;
    const int wrp  = threadIdx.x >> 5;
    const int row  = blockIdx.x * 8 + wrp;

    const float4* xr = (const float4*)(x + (size_t)row * D_MODEL);
    float4 v[8];
    #pragma unroll
    for (int i = 0; i < 8; i++) v[i] = xr[lane + 32 * i];

    float s = 0.f, ss = 0.f;
    #pragma unroll
    for (int i = 0; i < 8; i++) {
        s  += v[i].x + v[i].y + v[i].z + v[i].w;
        ss += v[i].x*v[i].x + v[i].y*v[i].y + v[i].z*v[i].z + v[i].w*v[i].w;
    }
    #pragma unroll
    for (int off = 16; off; off >>= 1) {
        s  += __shfl_xor_sync(0xffffffffu, s,  off);
        ss += __shfl_xor_sync(0xffffffffu, ss, off);
    }
    const float mu   = s * (1.0f / D_MODEL);
    const float var  = ss * (1.0f / D_MODEL) - mu * mu;
    const float rstd = rsqrtf(var + 1e-5f);

    __half* yr = y + (size_t)row * D_MODEL;
    #pragma unroll
    for (int i = 0; i < 8; i++) {
        const int e = lane + 32 * i;
        const float4 g4 = ((const float4*)gamma)[e];
        const float4 b4 = ((const float4*)beta)[e];
        const float ox = (v[i].x - mu) * rstd * g4.x + b4.x;
        const float oy = (v[i].y - mu) * rstd * g4.y + b4.y;
        const float oz = (v[i].z - mu) * rstd * g4.z + b4.z;
        const float ow = (v[i].w - mu) * rstd * g4.w + b4.w;
        __half2 h0 = __floats2half2_rn(ox, oy);
        __half2 h1 = __floats2half2_rn(oz, ow);
        uint2 o; o.x = *(uint32_t*)&h0; o.y = *(uint32_t*)&h1;
        *(uint2*)(yr + e * 4) = o;
    }
}

// ---------------- weight convert: f32 -> f16, 4 float4/thread (MLP=4) ----------------
__global__ void convert_h(const float* __restrict__ in, __half* __restrict__ out)
{
    const size_t b0 = (size_t)blockIdx.x * 4096 + threadIdx.x * 4;
    float4 v[4];
    #pragma unroll
    for (int j = 0; j < 4; j++) v[j] = *(const float4*)(in + b0 + j * 1024);
    #pragma unroll
    for (int j = 0; j < 4; j++) {
        __half2 a = __floats2half2_rn(v[j].x, v[j].y);
        __half2 b = __floats2half2_rn(v[j].z, v[j].w);
        uint2 o; o.x = *(uint32_t*)&a; o.y = *(uint32_t*)&b;
        *(uint2*)(out + b0 + j * 1024) = o;
    }
}

// qkv merge-convert + bias concat
__global__ void convert_qkv(const float* __restrict__ Wq, const float* __restrict__ Wk,
                            const float* __restrict__ Wv, float* __restrict__ bqkv,
                            const float* __restrict__ bq, const float* __restrict__ bk,
                            const float* __restrict__ bv, __half* __restrict__ out)
{
    const int k0 = blockIdx.x * 2;            // grid 512
    const int c  = threadIdx.x;               // 0..255
    const float* srcs[3] = { Wq, Wk, Wv };
    float4 v[2][3];
    #pragma unroll
    for (int r = 0; r < 2; r++)
        #pragma unroll
        for (int j = 0; j < 3; j++)
            v[r][j] = ((const float4*)(srcs[j] + (size_t)(k0 + r) * D_MODEL))[c];
    #pragma unroll
    for (int r = 0; r < 2; r++)
        #pragma unroll
        for (int j = 0; j < 3; j++) {
            __half2 a = __floats2half2_rn(v[r][j].x, v[r][j].y);
            __half2 b = __floats2half2_rn(v[r][j].z, v[r][j].w);
            uint2 o; o.x = *(uint32_t*)&a; o.y = *(uint32_t*)&b;
            *(uint2*)(out + (size_t)(k0 + r) * 3 * D_MODEL + j * D_MODEL + c * 4) = o;
        }
    if (blockIdx.x < 3) {
        const float* src = (blockIdx.x == 0) ? bq : (blockIdx.x == 1) ? bk : bv;
        #pragma unroll
        for (int j = 0; j < 4; j++)
            bqkv[blockIdx.x * 1024 + threadIdx.x + j * 256] = src[threadIdx.x + j * 256];
    }
}

// ---------------- fp16 tensor-core GEMM, 2 CTAs/SM, 6-stage k32 pipeline (R10/R11) ----------------
#define STG_BYTES 16384
#define GSM_TOTAL (6 * STG_BYTES)     /* 98304 */

template<bool RELU, bool RESID, bool HOUT>
__global__ __launch_bounds__(128, 2)
void gemm_h(const __half* __restrict__ Ah, const __half* __restrict__ Bh,
            const float* __restrict__ bias, const float* __restrict__ R,
            float* __restrict__ Cf, __half* __restrict__ Ch, int M, int N, int K)
{
    extern __shared__ char smem[];
    const uint32_t sb = smem_u32(smem);
    const int tid  = threadIdx.x;        // 0..127
    const int lane = tid & 31;
    const int wid  = tid >> 5;           // 0..3
    const int wm   = wid & 1;
    const int wn   = wid >> 1;           // 0..1

    const int m0 = blockIdx.y << 7;
    const int n0 = blockIdx.x << 7;

    const int rlA = lane & 15, clA = lane >> 4;
    const int kV = (lane & 7) + ((lane & 8) ? 8 : 0);
    const int cV = (lane >> 4) & 1;

    float acc[4][8][4];
    #pragma unroll
    for (int mi = 0; mi < 4; mi++)
        #pragma unroll
        for (int ni = 0; ni < 8; ni++)
            #pragma unroll
            for (int c = 0; c < 4; c++) acc[mi][ni][c] = 0.f;

    const int T = K >> 5;

    #define ISSUE_STAGE(s, buf) do { \
        const uint32_t b0_ = sb + (buf) * STG_BYTES; \
        _Pragma("unroll") \
        for (int j = 0; j < 4; j++) { \
            const int c_ = tid + j * 128, row_ = c_ >> 2, ch_ = c_ & 3; \
            CP16(b0_ + row_ * 64 + ((ch_ ^ ((row_ >> 1) & 3)) << 4), \
                 Ah + (size_t)(m0 + row_) * K + (s) * 32 + ch_ * 8); \
        } \
        _Pragma("unroll") \
        for (int j = 0; j < 4; j++) { \
            const int c_ = tid + j * 128, row_ = c_ >> 4, ch_ = c_ & 15; \
            const int ph_ = (ch_ & 8) | ((ch_ & 7) ^ (row_ & 7)); \
            CP16(b0_ + 8192 + row_ * 256 + (ph_ << 4), \
                 Bh + (size_t)((s) * 32 + row_) * N + n0 + ch_ * 8); \
        } \
    } while (0)

    #define LOAD_FRAGS(a_, b_, s_) do { \
        _Pragma("unroll") \
        for (int mi = 0; mi < 4; mi++) { \
            const int row = wm * 64 + mi * 16 + rlA; \
            LDSM4((a_)[mi][0], (a_)[mi][1], (a_)[mi][2], (a_)[mi][3], \
                  sA + row * 64 + (((2 * (s_) + clA) ^ ((row >> 1) & 3)) << 4)); \
        } \
        _Pragma("unroll") \
        for (int bb = 0; bb < 4; bb++) { \
            const int c = wn * 8 + 2 * bb + cV; \
            const int ph = (c & 8) | ((c & 7) ^ (kV & 7)); \
            LDSM4T((b_)[2*bb][0], (b_)[2*bb][1], (b_)[2*bb+1][0], (b_)[2*bb+1][1], \
                   sB + (16 * (s_) + kV) * 256 + (ph << 4)); \
        } \
    } while (0)

    #pragma unroll
    for (int i = 0; i < 5; i++) {
        if (i < T) ISSUE_STAGE(i, i);
        CP_COMMIT();
    }

    uint32_t af[2][4][4], bf[2][8][2];

    int cur = 0;
    for (int kt = 0; kt < T; kt++) {
        CP_WAIT4();
        __syncthreads();
        {
            int nb = cur + 5; if (nb >= 6) nb -= 6;
            if (kt + 5 < T) ISSUE_STAGE(kt + 5, nb);
            CP_COMMIT();
        }
        const uint32_t sA = sb + cur * STG_BYTES;
        const uint32_t sB = sA + 8192;

        LOAD_FRAGS(af[0], bf[0], 0);
        LOAD_FRAGS(af[1], bf[1], 1);
        #pragma unroll
        for (int s = 0; s < 2; s++) {
            #pragma unroll
            for (int mi = 0; mi < 4; mi++)
                #pragma unroll
                for (int ni = 0; ni < 8; ni++)
                    mma16(acc[mi][ni], af[s][mi], bf[s][ni]);
        }
        cur = (cur == 5) ? 0 : cur + 1;
    }
    #undef ISSUE_STAGE
    #undef LOAD_FRAGS

    // ---- epilogue ----
    const int g  = lane >> 2;
    const int t2 = lane & 3;
    #pragma unroll
    for (int ni = 0; ni < 8; ni++) {
        const int c = n0 + wn * 64 + ni * 8 + 2 * t2;
        const float2 bi = *(const float2*)&bias[c];
        #pragma unroll
        for (int mi = 0; mi < 4; mi++) {
            const int r0 = m0 + wm * 64 + mi * 16 + g;
            #pragma unroll
            for (int h = 0; h < 2; h++) {
                const int rr = r0 + h * 8;
                float vx = acc[mi][ni][2 * h]     + bi.x;
                float vy = acc[mi][ni][2 * h + 1] + bi.y;
                if (RELU) { vx = fmaxf(vx, 0.f); vy = fmaxf(vy, 0.f); }
                const size_t idx = (size_t)rr * N + c;
                if (RESID) {
                    const float2 rs = *(const float2*)&R[idx];
                    vx += rs.x; vy += rs.y;
                }
                if (HOUT) {
                    __half2 hv = __floats2half2_rn(vx, vy);
                    *(uint32_t*)&Ch[idx] = *(uint32_t*)&hv;
                } else {
                    float2 o; o.x = vx; o.y = vy;
                    *(float2*)&Cf[idx] = o;
                }
            }
        }
    }
}

// ---------------- fp16 flash attention, register-resident P, 2 CTAs/SM (R11) ----------------
#define ATT_STG  16384
#define ATT_SMEM (16384 + 3 * ATT_STG)   /* 65536 */

__global__ __launch_bounds__(256, 2)
void attn_h(const __half* __restrict__ Qg, const __half* __restrict__ Kg,
            const __half* __restrict__ Vg, __half* __restrict__ O, int ld)
{
    extern __shared__ char smem[];
    const uint32_t sb = smem_u32(smem);
    const int tid  = threadIdx.x;
    const int lane = tid & 31;
    const int wid  = tid >> 5;
    const int g    = lane >> 2;
    const int t    = lane & 3;
    const int swz  = lane & 7;

    const int bh = blockIdx.y;
    const int b  = bh >> 4;
    const int h  = bh & 15;
    const int q0 = blockIdx.x << 7;

    const size_t base  = (size_t)b * SEQ * ld + (size_t)h * DK;
    const size_t obase = (size_t)b * SEQ * D_MODEL + (size_t)h * DK;

    #pragma unroll
    for (int p = 0; p < 4; p++) {
        const int c = tid + p * 256, row = c >> 3, ch = c & 7;
        *(uint4*)(smem + row * 128 + ((ch ^ (row & 7)) << 4)) =
            *(const uint4*)(Qg + base + (size_t)(q0 + row) * ld + ch * 8);
    }
    __syncthreads();

    uint32_t aq[4][4];
    {
        const int rowA = wid * 16 + (lane & 15);
        const int clA  = lane >> 4;
        #pragma unroll
        for (int kb = 0; kb < 4; kb++)
            LDSM4(aq[kb][0], aq[kb][1], aq[kb][2], aq[kb][3],
                  sb + rowA * 128 + (((2 * kb + clA) ^ swz) << 4));
    }

    const int rlB = (lane & 7) + ((lane >> 4) << 3);
    const int clB = (lane >> 3) & 1;
    const int kV  = (lane & 7) + ((lane & 8) ? 8 : 0);
    const int cV  = (lane >> 4) & 1;

    float m0v = -1e30f, m1v = -1e30f, l0 = 0.f, l1 = 0.f;
    float oacc[8][4];
    #pragma unroll
    for (int ni = 0; ni < 8; ni++)
        #pragma unroll
        for (int c = 0; c < 4; c++) oacc[ni][c] = 0.f;

    #define ISSUE_KV(s, buf) do { \
        const uint32_t kb_ = sb + 16384 + (buf) * ATT_STG; \
        _Pragma("unroll") \
        for (int j = 0; j < 2; j++) { \
            const int c_ = tid + j * 256, row_ = c_ >> 3, ch_ = c_ & 7; \
            const uint32_t off_ = row_ * 128 + ((ch_ ^ (row_ & 7)) << 4); \
            const size_t gsrc = base + (size_t)((s) * 64 + row_) * ld + ch_ * 8; \
            CP16(kb_ + off_,        Kg + gsrc); \
            CP16(kb_ + 8192 + off_, Vg + gsrc); \
        } \
    } while (0)

    ISSUE_KV(0, 0); CP_COMMIT();
    ISSUE_KV(1, 1); CP_COMMIT();

    int cur = 0;
    const int T = SEQ / 64;
    for (int kt = 0; kt < T; kt++) {
        CP_WAIT1();
        __syncthreads();
        {
            int nb = cur + 2; if (nb >= 3) nb -= 3;
            if (kt + 2 < T) ISSUE_KV(kt + 2, nb);
            CP_COMMIT();
        }
        const uint32_t kbuf = sb + 16384 + cur * ATT_STG;
        const uint32_t vbuf = kbuf + 8192;

        float sacc[8][4];
        #pragma unroll
        for (int ni = 0; ni < 8; ni++)
            #pragma unroll
            for (int c = 0; c < 4; c++) sacc[ni][c] = 0.f;

        #pragma unroll
        for (int kb = 0; kb < 4; kb++) {
            uint32_t bf[8][2];
            #pragma unroll
            for (int a = 0; a < 4; a++) {
                const int row = 16 * a + rlB;
                LDSM4(bf[2*a][0], bf[2*a][1], bf[2*a+1][0], bf[2*a+1][1],
                      kbuf + row * 128 + (((2 * kb + clB) ^ swz) << 4));
            }
            #pragma unroll
            for (int ni = 0; ni < 8; ni++)
                mma16(sacc[ni], aq[kb], bf[ni]);
        }

        #pragma unroll
        for (int ni = 0; ni < 8; ni++) {
            sacc[ni][0] *= 0.125f; sacc[ni][1] *= 0.125f;
            sacc[ni][2] *= 0.125f; sacc[ni][3] *= 0.125f;
        }
        float mx0 = -1e30f, mx1 = -1e30f;
        #pragma unroll
        for (int ni = 0; ni < 8; ni++) {
            mx0 = fmaxf(mx0, fmaxf(sacc[ni][0], sacc[ni][1]));
            mx1 = fmaxf(mx1, fmaxf(sacc[ni][2], sacc[ni][3]));
        }
        mx0 = fmaxf(mx0, __shfl_xor_sync(0xffffffffu, mx0, 1));
        mx0 = fmaxf(mx0, __shfl_xor_sync(0xffffffffu, mx0, 2));
        mx1 = fmaxf(mx1, __shfl_xor_sync(0xffffffffu, mx1, 1));
        mx1 = fmaxf(mx1, __shfl_xor_sync(0xffffffffu, mx1, 2));

        const float mn0 = fmaxf(m0v, mx0);
        const float mn1 = fmaxf(m1v, mx1);
        const float al0 = __expf(m0v - mn0);
        const float al1 = __expf(m1v - mn1);
        m0v = mn0; m1v = mn1;

        uint32_t pa[8][2];
        float sum0 = 0.f, sum1 = 0.f;
        #pragma unroll
        for (int ni = 0; ni < 8; ni++) {
            const float p0 = __expf(sacc[ni][0] - mn0);
            const float p1 = __expf(sacc[ni][1] - mn0);
            const float p2 = __expf(sacc[ni][2] - mn1);
            const float p3 = __expf(sacc[ni][3] - mn1);
            sum0 += p0 + p1; sum1 += p2 + p3;
            __half2 h0 = __floats2half2_rn(p0, p1);
            __half2 h1 = __floats2half2_rn(p2, p3);
            pa[ni][0] = *(uint32_t*)&h0;
            pa[ni][1] = *(uint32_t*)&h1;
        }
        sum0 += __shfl_xor_sync(0xffffffffu, sum0, 1);
        sum0 += __shfl_xor_sync(0xffffffffu, sum0, 2);
        sum1 += __shfl_xor_sync(0xffffffffu, sum1, 1);
        sum1 += __shfl_xor_sync(0xffffffffu, sum1, 2);
        l0 = l0 * al0 + sum0;
        l1 = l1 * al1 + sum1;

        #pragma unroll
        for (int ni = 0; ni < 8; ni++) {
            oacc[ni][0] *= al0; oacc[ni][1] *= al0;
            oacc[ni][2] *= al1; oacc[ni][3] *= al1;
        }

        #pragma unroll
        for (int kk = 0; kk < 4; kk++) {
            uint32_t bv[8][2];
            #pragma unroll
            for (int bb = 0; bb < 4; bb++) {
                const int key = 16 * kk + kV;
                LDSM4T(bv[2*bb][0], bv[2*bb][1], bv[2*bb+1][0], bv[2*bb+1][1],
                       vbuf + key * 128 + (((2 * bb + cV) ^ swz) << 4));
            }
            uint32_t ap[4] = { pa[2*kk][0], pa[2*kk][1], pa[2*kk+1][0], pa[2*kk+1][1] };
            #pragma unroll
            for (int ni = 0; ni < 8; ni++)
                mma16(oacc[ni], ap, bv[ni]);
        }

        cur = (cur == 2) ? 0 : cur + 1;
    }
    #undef ISSUE_KV

    const float inv0 = 1.f / l0;
    const float inv1 = 1.f / l1;
    const size_t row0 = obase + (size_t)(q0 + wid * 16 + g) * D_MODEL;
    const size_t row1 = row0 + (size_t)8 * D_MODEL;
    #pragma unroll
    for (int ni = 0; ni < 8; ni++) {
        const int c = ni * 8 + 2 * t;
        __half2 h0 = __floats2half2_rn(oacc[ni][0] * inv0, oacc[ni][1] * inv0);
        __half2 h1 = __floats2half2_rn(oacc[ni][2] * inv1, oacc[ni][3] * inv1);
        *(uint32_t*)&O[row0 + c] = *(uint32_t*)&h0;
        *(uint32_t*)&O[row1 + c] = *(uint32_t*)&h1;
    }
}

// ---------------- launch ----------------
extern "C" void kernel_launch(void* const* d_in, const int* in_sizes, int n_in,
                              void* d_out, int out_size)
{
    const float* x    = (const float*)d_in[0];
    const float* ln1g = (const float*)d_in[1];
    const float* ln1b = (const float*)d_in[2];
    const float* ln2g = (const float*)d_in[3];
    const float* ln2b = (const float*)d_in[4];
    const float* Wq = (const float*)d_in[5];
    const float* bq = (const float*)d_in[6];
    const float* Wk = (const float*)d_in[7];
    const float* bk = (const float*)d_in[8];
    const float* Wv = (const float*)d_in[9];
    const float* bv = (const float*)d_in[10];
    const float* Wo = (const float*)d_in[11];
    const float* bo = (const float*)d_in[12];
    const float* W1 = (const float*)d_in[13];
    const float* b1 = (const float*)d_in[14];
    const float* W2 = (const float*)d_in[15];
    const float* b2 = (const float*)d_in[16];
    float* out = (float*)d_out;

    __half *xnh, *qkvh, *ctxh, *ffh, *wqkvh, *woh, *w1h, *w2h;
    float *x1, *bqkv;
    cudaGetSymbolAddress((void**)&xnh,   g_xnh);
    cudaGetSymbolAddress((void**)&qkvh,  g_qkvh);
    cudaGetSymbolAddress((void**)&ctxh,  g_ctxh);
    cudaGetSymbolAddress((void**)&x1,    g_x1);
    cudaGetSymbolAddress((void**)&ffh,   g_ffh);
    cudaGetSymbolAddress((void**)&wqkvh, g_wqkvh);
    cudaGetSymbolAddress((void**)&woh,   g_woh);
    cudaGetSymbolAddress((void**)&w1h,   g_w1h);
    cudaGetSymbolAddress((void**)&w2h,   g_w2h);
    cudaGetSymbolAddress((void**)&bqkv,  g_bqkv);

    cudaFuncSetAttribute(attn_h, cudaFuncAttributeMaxDynamicSharedMemorySize, ATT_SMEM);
    cudaFuncSetAttribute(gemm_h<false,false,true>,  cudaFuncAttributeMaxDynamicSharedMemorySize, GSM_TOTAL);
    cudaFuncSetAttribute(gemm_h<false,true,false>,  cudaFuncAttributeMaxDynamicSharedMemorySize, GSM_TOTAL);
    cudaFuncSetAttribute(gemm_h<true,false,true>,   cudaFuncAttributeMaxDynamicSharedMemorySize, GSM_TOTAL);

    // ---- fork: side stream converts Wo/W1/W2 while main chain runs ----
    cudaStream_t s1;
    cudaStreamCreateWithFlags(&s1, cudaStreamNonBlocking);
    cudaEvent_t eFork, eJoin;
    cudaEventCreateWithFlags(&eFork, cudaEventDisableTiming);
    cudaEventCreateWithFlags(&eJoin, cudaEventDisableTiming);

    cudaEventRecord(eFork, 0);
    cudaStreamWaitEvent(s1, eFork, 0);

    // side stream: weight converts needed only from step 4 onward
    convert_h<<<(D_MODEL*D_MODEL)/4096, 256, 0, s1>>>(Wo, woh);
    convert_h<<<(D_MODEL*D_FF)/4096, 256, 0, s1>>>(W1, w1h);
    convert_h<<<(D_FF*D_MODEL)/4096, 256, 0, s1>>>(W2, w2h);
    cudaEventRecord(eJoin, s1);

    // main stream: qkv convert + LN1 + QKV GEMM + attention
    convert_qkv<<<512, 256>>>(Wq, Wk, Wv, bqkv, bq, bk, bv, wqkvh);
    ln_kernel<<<NTOK/8, 256>>>(x, ln1g, ln1b, xnh);
    gemm_h<false,false,true><<<dim3(3*D_MODEL/128, NTOK/128), 128, GSM_TOTAL>>>(
        xnh, wqkvh, bqkv, nullptr, nullptr, qkvh, NTOK, 3*D_MODEL, D_MODEL);
    attn_h<<<dim3(SEQ/128, BATCH*NHEAD), 256, ATT_SMEM>>>(
        qkvh, qkvh + D_MODEL, qkvh + 2*D_MODEL, ctxh, 3*D_MODEL);

    // join before the Wo GEMM
    cudaStreamWaitEvent(0, eJoin, 0);

    // 4) x1 = x + ctx @ Wo + bo  (f32 out)
    gemm_h<false,true,false><<<dim3(D_MODEL/128, NTOK/128), 128, GSM_TOTAL>>>(
        ctxh, woh, bo, x, x1, nullptr, NTOK, D_MODEL, D_MODEL);
    // 5) xn = LN2(x1)  (fp16 out)
    ln_kernel<<<NTOK/8, 256>>>(x1, ln2g, ln2b, xnh);
    // 6) ffh = relu(xn @ W1 + b1)  (fp16 out)
    gemm_h<true,false,true><<<dim3(D_FF/128, NTOK/128), 128, GSM_TOTAL>>>(
        xnh, w1h, b1, nullptr, nullptr, ffh, NTOK, D_FF, D_MODEL);
    // 7) out = x1 + ffh @ W2 + b2  (f32 out)
    gemm_h<false,true,false><<<dim3(D_MODEL/128, NTOK/128), 128, GSM_TOTAL>>>(
        ffh, w2h, b2, x1, out, nullptr, NTOK, D_MODEL, D_FF);

    cudaEventDestroy(eFork);
    cudaEventDestroy(eJoin);
    cudaStreamDestroy(s1);
}

// round 14
// speedup vs baseline: 1.0204x; 1.0062x over previous
#include <cuda_runtime.h>
#include <cuda_fp16.h>
#include <cstdint>

#define D_MODEL 1024
#define D_FF    4096
#define SEQ     2048
#define BATCH   4
#define NTOK    (BATCH*SEQ)   /* 8192 */
#define NHEAD   16
#define DK      64

// ---------------- scratch (static device globals; no allocation) ----------------
__device__ __half g_xnh  [(size_t)NTOK*D_MODEL];
__device__ __half g_qkvh [(size_t)NTOK*3*D_MODEL];
__device__ __half g_ctxh [(size_t)NTOK*D_MODEL];
__device__ float  g_x1   [(size_t)NTOK*D_MODEL];
__device__ __half g_ffh  [(size_t)NTOK*D_FF];
__device__ __half g_wqkvh[(size_t)D_MODEL*3*D_MODEL];   // [K=1024][N=3072]
__device__ __half g_woh  [(size_t)D_MODEL*D_MODEL];     // [K][N]
__device__ __half g_w1h  [(size_t)D_MODEL*D_FF];        // [1024][4096]
__device__ __half g_w2h  [(size_t)D_FF*D_MODEL];        // [4096][1024]
__device__ float  g_bqkv [3*D_MODEL];

// ---------------- PTX helpers ----------------
__device__ __forceinline__ uint32_t smem_u32(const void* p) {
    uint32_t a;
    asm("{ .reg .u64 t; cvta.to.shared.u64 t, %1; cvt.u32.u64 %0, t; }"
        : "=r"(a) : "l"(p));
    return a;
}

#define LDSM4(r0, r1, r2, r3, a) \
    asm volatile("ldmatrix.sync.aligned.m8n8.x4.shared.b16 {%0,%1,%2,%3}, [%4];" \
        : "=r"(r0), "=r"(r1), "=r"(r2), "=r"(r3) : "r"(a))
#define LDSM4T(r0, r1, r2, r3, a) \
    asm volatile("ldmatrix.sync.aligned.m8n8.x4.trans.shared.b16 {%0,%1,%2,%3}, [%4];" \
        : "=r"(r0), "=r"(r1), "=r"(r2), "=r"(r3) : "r"(a))

#define CP16(dst, src) \
    asm volatile("cp.async.cg.shared.global [%0], [%1], 16;" :: "r"(dst), "l"(src))
#define CP_COMMIT() asm volatile("cp.async.commit_group;" ::: "memory")
#define CP_WAIT1()  asm volatile("cp.async.wait_group 1;" ::: "memory")
#define CP_WAIT4()  asm volatile("cp.async.wait_group 4;" ::: "memory")

// fp16 MMA, fp32 accum: D(16x8) += A(16x16) @ B(16x8)
__device__ __forceinline__ void mma16(float* d, const uint32_t* a, const uint32_t* b) {
    asm volatile(
        "mma.sync.aligned.m16n8k16.row.col.f32.f16.f16.f32 "
        "{%0,%1,%2,%3}, {%4,%5,%6,%7}, {%8,%9}, {%0,%1,%2,%3};"
        : "+f"(d[0]), "+f"(d[1]), "+f"(d[2]), "+f"(d[3])
        : "r"(a[0]), "r"(a[1]), "r"(a[2]), "r"(a[3]), "r"(b[0]), "r"(b[1]));
}

// ---------------- LayerNorm: warp-per-row, MLP=8, f32 in fp16 out ----------------
__global__ void ln_kernel(const float* __restrict__ x,
                          const float* __restrict__ gamma,
                          const float* __restrict__ beta,
                          __half* __restrict__ y)
{
    const int lane = threadIdx.x & 31;
    const int wrp  = threadIdx.x >> 5;
    const int row  = blockIdx.x * 8 + wrp;

    const float4* xr = (const float4*)(x + (size_t)row * D_MODEL);
    float4 v[8];
    #pragma unroll
    for (int i = 0; i < 8; i++) v[i] = xr[lane + 32 * i];

    float s = 0.f, ss = 0.f;
    #pragma unroll
    for (int i = 0; i < 8; i++) {
        s  += v[i].x + v[i].y + v[i].z + v[i].w;
        ss += v[i].x*v[i].x + v[i].y*v[i].y + v[i].z*v[i].z + v[i].w*v[i].w;
    }
    #pragma unroll
    for (int off = 16; off; off >>= 1) {
        s  += __shfl_xor_sync(0xffffffffu, s,  off);
        ss += __shfl_xor_sync(0xffffffffu, ss, off);
    }
    const float mu   = s * (1.0f / D_MODEL);
    const float var  = ss * (1.0f / D_MODEL) - mu * mu;
    const float rstd = rsqrtf(var + 1e-5f);

    __half* yr = y + (size_t)row * D_MODEL;
    #pragma unroll
    for (int i = 0; i < 8; i++) {
        const int e = lane + 32 * i;
        const float4 g4 = ((const float4*)gamma)[e];
        const float4 b4 = ((const float4*)beta)[e];
        const float ox = (v[i].x - mu) * rstd * g4.x + b4.x;
        const float oy = (v[i].y - mu) * rstd * g4.y + b4.y;
        const float oz = (v[i].z - mu) * rstd * g4.z + b4.z;
        const float ow = (v[i].w - mu) * rstd * g4.w + b4.w;
        __half2 h0 = __floats2half2_rn(ox, oy);
        __half2 h1 = __floats2half2_rn(oz, ow);
        uint2 o; o.x = *(uint32_t*)&h0; o.y = *(uint32_t*)&h1;
        *(uint2*)(yr + e * 4) = o;
    }
}

// ---------------- weight convert: f32 -> f16, 4 float4/thread (MLP=4) ----------------
__global__ void convert_h(const float* __restrict__ in, __half* __restrict__ out)
{
    const size_t b0 = (size_t)blockIdx.x * 4096 + threadIdx.x * 4;
    float4 v[4];
    #pragma unroll
    for (int j = 0; j < 4; j++) v[j] = *(const float4*)(in + b0 + j * 1024);
    #pragma unroll
    for (int j = 0; j < 4; j++) {
        __half2 a = __floats2half2_rn(v[j].x, v[j].y);
        __half2 b = __floats2half2_rn(v[j].z, v[j].w);
        uint2 o; o.x = *(uint32_t*)&a; o.y = *(uint32_t*)&b;
        *(uint2*)(out + b0 + j * 1024) = o;
    }
}

// qkv merge-convert + bias concat
__global__ void convert_qkv(const float* __restrict__ Wq, const float* __restrict__ Wk,
                            const float* __restrict__ Wv, float* __restrict__ bqkv,
                            const float* __restrict__ bq, const float* __restrict__ bk,
                            const float* __restrict__ bv, __half* __restrict__ out)
{
    const int k0 = blockIdx.x * 2;            // grid 512
    const int c  = threadIdx.x;               // 0..255
    const float* srcs[3] = { Wq, Wk, Wv };
    float4 v[2][3];
    #pragma unroll
    for (int r = 0; r < 2; r++)
        #pragma unroll
        for (int j = 0; j < 3; j++)
            v[r][j] = ((const float4*)(srcs[j] + (size_t)(k0 + r) * D_MODEL))[c];
    #pragma unroll
    for (int r = 0; r < 2; r++)
        #pragma unroll
        for (int j = 0; j < 3; j++) {
            __half2 a = __floats2half2_rn(v[r][j].x, v[r][j].y);
            __half2 b = __floats2half2_rn(v[r][j].z, v[r][j].w);
            uint2 o; o.x = *(uint32_t*)&a; o.y = *(uint32_t*)&b;
            *(uint2*)(out + (size_t)(k0 + r) * 3 * D_MODEL + j * D_MODEL + c * 4) = o;
        }
    if (blockIdx.x < 3) {
        const float* src = (blockIdx.x == 0) ? bq : (blockIdx.x == 1) ? bk : bv;
        #pragma unroll
        for (int j = 0; j < 4; j++)
            bqkv[blockIdx.x * 1024 + threadIdx.x + j * 256] = src[threadIdx.x + j * 256];
    }
}

// ---------------- fp16 tensor-core GEMM, 2 CTAs/SM, 6-stage k32 pipeline (R10/R11) ----------------
#define STG_BYTES 16384
#define GSM_TOTAL (6 * STG_BYTES)     /* 98304 */

template<bool RELU, bool RESID, bool HOUT>
__global__ __launch_bounds__(128, 2)
void gemm_h(const __half* __restrict__ Ah, const __half* __restrict__ Bh,
            const float* __restrict__ bias, const float* __restrict__ R,
            float* __restrict__ Cf, __half* __restrict__ Ch, int M, int N, int K)
{
    extern __shared__ char smem[];
    const uint32_t sb = smem_u32(smem);
    const int tid  = threadIdx.x;        // 0..127
    const int lane = tid & 31;
    const int wid  = tid >> 5;           // 0..3
    const int wm   = wid & 1;
    const int wn   = wid >> 1;           // 0..1

    const int m0 = blockIdx.y << 7;
    const int n0 = blockIdx.x << 7;

    const int rlA = lane & 15, clA = lane >> 4;
    const int kV = (lane & 7) + ((lane & 8) ? 8 : 0);
    const int cV = (lane >> 4) & 1;

    float acc[4][8][4];
    #pragma unroll
    for (int mi = 0; mi < 4; mi++)
        #pragma unroll
        for (int ni = 0; ni < 8; ni++)
            #pragma unroll
            for (int c = 0; c < 4; c++) acc[mi][ni][c] = 0.f;

    const int T = K >> 5;

    #define ISSUE_STAGE(s, buf) do { \
        const uint32_t b0_ = sb + (buf) * STG_BYTES; \
        _Pragma("unroll") \
        for (int j = 0; j < 4; j++) { \
            const int c_ = tid + j * 128, row_ = c_ >> 2, ch_ = c_ & 3; \
            CP16(b0_ + row_ * 64 + ((ch_ ^ ((row_ >> 1) & 3)) << 4), \
                 Ah + (size_t)(m0 + row_) * K + (s) * 32 + ch_ * 8); \
        } \
        _Pragma("unroll") \
        for (int j = 0; j < 4; j++) { \
            const int c_ = tid + j * 128, row_ = c_ >> 4, ch_ = c_ & 15; \
            const int ph_ = (ch_ & 8) | ((ch_ & 7) ^ (row_ & 7)); \
            CP16(b0_ + 8192 + row_ * 256 + (ph_ << 4), \
                 Bh + (size_t)((s) * 32 + row_) * N + n0 + ch_ * 8); \
        } \
    } while (0)

    #define LOAD_FRAGS(a_, b_, s_) do { \
        _Pragma("unroll") \
        for (int mi = 0; mi < 4; mi++) { \
            const int row = wm * 64 + mi * 16 + rlA; \
            LDSM4((a_)[mi][0], (a_)[mi][1], (a_)[mi][2], (a_)[mi][3], \
                  sA + row * 64 + (((2 * (s_) + clA) ^ ((row >> 1) & 3)) << 4)); \
        } \
        _Pragma("unroll") \
        for (int bb = 0; bb < 4; bb++) { \
            const int c = wn * 8 + 2 * bb + cV; \
            const int ph = (c & 8) | ((c & 7) ^ (kV & 7)); \
            LDSM4T((b_)[2*bb][0], (b_)[2*bb][1], (b_)[2*bb+1][0], (b_)[2*bb+1][1], \
                   sB + (16 * (s_) + kV) * 256 + (ph << 4)); \
        } \
    } while (0)

    #pragma unroll
    for (int i = 0; i < 5; i++) {
        if (i < T) ISSUE_STAGE(i, i);
        CP_COMMIT();
    }

    uint32_t af[2][4][4], bf[2][8][2];

    int cur = 0;
    for (int kt = 0; kt < T; kt++) {
        CP_WAIT4();
        __syncthreads();
        {
            int nb = cur + 5; if (nb >= 6) nb -= 6;
            if (kt + 5 < T) ISSUE_STAGE(kt + 5, nb);
            CP_COMMIT();
        }
        const uint32_t sA = sb + cur * STG_BYTES;
        const uint32_t sB = sA + 8192;

        LOAD_FRAGS(af[0], bf[0], 0);
        LOAD_FRAGS(af[1], bf[1], 1);
        #pragma unroll
        for (int s = 0; s < 2; s++) {
            #pragma unroll
            for (int mi = 0; mi < 4; mi++)
                #pragma unroll
                for (int ni = 0; ni < 8; ni++)
                    mma16(acc[mi][ni], af[s][mi], bf[s][ni]);
        }
        cur = (cur == 5) ? 0 : cur + 1;
    }
    #undef ISSUE_STAGE
    #undef LOAD_FRAGS

    // ---- epilogue ----
    const int g  = lane >> 2;
    const int t2 = lane & 3;
    #pragma unroll
    for (int ni = 0; ni < 8; ni++) {
        const int c = n0 + wn * 64 + ni * 8 + 2 * t2;
        const float2 bi = *(const float2*)&bias[c];
        #pragma unroll
        for (int mi = 0; mi < 4; mi++) {
            const int r0 = m0 + wm * 64 + mi * 16 + g;
            #pragma unroll
            for (int h = 0; h < 2; h++) {
                const int rr = r0 + h * 8;
                float vx = acc[mi][ni][2 * h]     + bi.x;
                float vy = acc[mi][ni][2 * h + 1] + bi.y;
                if (RELU) { vx = fmaxf(vx, 0.f); vy = fmaxf(vy, 0.f); }
                const size_t idx = (size_t)rr * N + c;
                if (RESID) {
                    const float2 rs = *(const float2*)&R[idx];
                    vx += rs.x; vy += rs.y;
                }
                if (HOUT) {
                    __half2 hv = __floats2half2_rn(vx, vy);
                    *(uint32_t*)&Ch[idx] = *(uint32_t*)&hv;
                } else {
                    float2 o; o.x = vx; o.y = vy;
                    *(float2*)&Cf[idx] = o;
                }
            }
        }
    }
}

// ---------------- fp16 flash attention, register-resident P, 2 CTAs/SM (R11) ----------------
#define ATT_STG  16384
#define ATT_SMEM (16384 + 3 * ATT_STG)   /* 65536 */

__global__ __launch_bounds__(256, 2)
void attn_h(const __half* __restrict__ Qg, const __half* __restrict__ Kg,
            const __half* __restrict__ Vg, __half* __restrict__ O, int ld)
{
    extern __shared__ char smem[];
    const uint32_t sb = smem_u32(smem);
    const int tid  = threadIdx.x;
    const int lane = tid & 31;
    const int wid  = tid >> 5;
    const int g    = lane >> 2;
    const int t    = lane & 3;
    const int swz  = lane & 7;

    const int bh = blockIdx.y;
    const int b  = bh >> 4;
    const int h  = bh & 15;
    const int q0 = blockIdx.x << 7;

    const size_t base  = (size_t)b * SEQ * ld + (size_t)h * DK;
    const size_t obase = (size_t)b * SEQ * D_MODEL + (size_t)h * DK;

    #pragma unroll
    for (int p = 0; p < 4; p++) {
        const int c = tid + p * 256, row = c >> 3, ch = c & 7;
        *(uint4*)(smem + row * 128 + ((ch ^ (row & 7)) << 4)) =
            *(const uint4*)(Qg + base + (size_t)(q0 + row) * ld + ch * 8);
    }
    __syncthreads();

    uint32_t aq[4][4];
    {
        const int rowA = wid * 16 + (lane & 15);
        const int clA  = lane >> 4;
        #pragma unroll
        for (int kb = 0; kb < 4; kb++)
            LDSM4(aq[kb][0], aq[kb][1], aq[kb][2], aq[kb][3],
                  sb + rowA * 128 + (((2 * kb + clA) ^ swz) << 4));
    }

    const int rlB = (lane & 7) + ((lane >> 4) << 3);
    const int clB = (lane >> 3) & 1;
    const int kV  = (lane & 7) + ((lane & 8) ? 8 : 0);
    const int cV  = (lane >> 4) & 1;

    float m0v = -1e30f, m1v = -1e30f, l0 = 0.f, l1 = 0.f;
    float oacc[8][4];
    #pragma unroll
    for (int ni = 0; ni < 8; ni++)
        #pragma unroll
        for (int c = 0; c < 4; c++) oacc[ni][c] = 0.f;

    #define ISSUE_KV(s, buf) do { \
        const uint32_t kb_ = sb + 16384 + (buf) * ATT_STG; \
        _Pragma("unroll") \
        for (int j = 0; j < 2; j++) { \
            const int c_ = tid + j * 256, row_ = c_ >> 3, ch_ = c_ & 7; \
            const uint32_t off_ = row_ * 128 + ((ch_ ^ (row_ & 7)) << 4); \
            const size_t gsrc = base + (size_t)((s) * 64 + row_) * ld + ch_ * 8; \
            CP16(kb_ + off_,        Kg + gsrc); \
            CP16(kb_ + 8192 + off_, Vg + gsrc); \
        } \
    } while (0)

    ISSUE_KV(0, 0); CP_COMMIT();
    ISSUE_KV(1, 1); CP_COMMIT();

    int cur = 0;
    const int T = SEQ / 64;
    for (int kt = 0; kt < T; kt++) {
        CP_WAIT1();
        __syncthreads();
        {
            int nb = cur + 2; if (nb >= 3) nb -= 3;
            if (kt + 2 < T) ISSUE_KV(kt + 2, nb);
            CP_COMMIT();
        }
        const uint32_t kbuf = sb + 16384 + cur * ATT_STG;
        const uint32_t vbuf = kbuf + 8192;

        float sacc[8][4];
        #pragma unroll
        for (int ni = 0; ni < 8; ni++)
            #pragma unroll
            for (int c = 0; c < 4; c++) sacc[ni][c] = 0.f;

        #pragma unroll
        for (int kb = 0; kb < 4; kb++) {
            uint32_t bf[8][2];
            #pragma unroll
            for (int a = 0; a < 4; a++) {
                const int row = 16 * a + rlB;
                LDSM4(bf[2*a][0], bf[2*a][1], bf[2*a+1][0], bf[2*a+1][1],
                      kbuf + row * 128 + (((2 * kb + clB) ^ swz) << 4));
            }
            #pragma unroll
            for (int ni = 0; ni < 8; ni++)
                mma16(sacc[ni], aq[kb], bf[ni]);
        }

        #pragma unroll
        for (int ni = 0; ni < 8; ni++) {
            sacc[ni][0] *= 0.125f; sacc[ni][1] *= 0.125f;
            sacc[ni][2] *= 0.125f; sacc[ni][3] *= 0.125f;
        }
        float mx0 = -1e30f, mx1 = -1e30f;
        #pragma unroll
        for (int ni = 0; ni < 8; ni++) {
            mx0 = fmaxf(mx0, fmaxf(sacc[ni][0], sacc[ni][1]));
            mx1 = fmaxf(mx1, fmaxf(sacc[ni][2], sacc[ni][3]));
        }
        mx0 = fmaxf(mx0, __shfl_xor_sync(0xffffffffu, mx0, 1));
        mx0 = fmaxf(mx0, __shfl_xor_sync(0xffffffffu, mx0, 2));
        mx1 = fmaxf(mx1, __shfl_xor_sync(0xffffffffu, mx1, 1));
        mx1 = fmaxf(mx1, __shfl_xor_sync(0xffffffffu, mx1, 2));

        const float mn0 = fmaxf(m0v, mx0);
        const float mn1 = fmaxf(m1v, mx1);
        const float al0 = __expf(m0v - mn0);
        const float al1 = __expf(m1v - mn1);
        m0v = mn0; m1v = mn1;

        uint32_t pa[8][2];
        float sum0 = 0.f, sum1 = 0.f;
        #pragma unroll
        for (int ni = 0; ni < 8; ni++) {
            const float p0 = __expf(sacc[ni][0] - mn0);
            const float p1 = __expf(sacc[ni][1] - mn0);
            const float p2 = __expf(sacc[ni][2] - mn1);
            const float p3 = __expf(sacc[ni][3] - mn1);
            sum0 += p0 + p1; sum1 += p2 + p3;
            __half2 h0 = __floats2half2_rn(p0, p1);
            __half2 h1 = __floats2half2_rn(p2, p3);
            pa[ni][0] = *(uint32_t*)&h0;
            pa[ni][1] = *(uint32_t*)&h1;
        }
        sum0 += __shfl_xor_sync(0xffffffffu, sum0, 1);
        sum0 += __shfl_xor_sync(0xffffffffu, sum0, 2);
        sum1 += __shfl_xor_sync(0xffffffffu, sum1, 1);
        sum1 += __shfl_xor_sync(0xffffffffu, sum1, 2);
        l0 = l0 * al0 + sum0;
        l1 = l1 * al1 + sum1;

        #pragma unroll
        for (int ni = 0; ni < 8; ni++) {
            oacc[ni][0] *= al0; oacc[ni][1] *= al0;
            oacc[ni][2] *= al1; oacc[ni][3] *= al1;
        }

        #pragma unroll
        for (int kk = 0; kk < 4; kk++) {
            uint32_t bv[8][2];
            #pragma unroll
            for (int bb = 0; bb < 4; bb++) {
                const int key = 16 * kk + kV;
                LDSM4T(bv[2*bb][0], bv[2*bb][1], bv[2*bb+1][0], bv[2*bb+1][1],
                       vbuf + key * 128 + (((2 * bb + cV) ^ swz) << 4));
            }
            uint32_t ap[4] = { pa[2*kk][0], pa[2*kk][1], pa[2*kk+1][0], pa[2*kk+1][1] };
            #pragma unroll
            for (int ni = 0; ni < 8; ni++)
                mma16(oacc[ni], ap, bv[ni]);
        }

        cur = (cur == 2) ? 0 : cur + 1;
    }
    #undef ISSUE_KV

    const float inv0 = 1.f / l0;
    const float inv1 = 1.f / l1;
    const size_t row0 = obase + (size_t)(q0 + wid * 16 + g) * D_MODEL;
    const size_t row1 = row0 + (size_t)8 * D_MODEL;
    #pragma unroll
    for (int ni = 0; ni < 8; ni++) {
        const int c = ni * 8 + 2 * t;
        __half2 h0 = __floats2half2_rn(oacc[ni][0] * inv0, oacc[ni][1] * inv0);
        __half2 h1 = __floats2half2_rn(oacc[ni][2] * inv1, oacc[ni][3] * inv1);
        *(uint32_t*)&O[row0 + c] = *(uint32_t*)&h0;
        *(uint32_t*)&O[row1 + c] = *(uint32_t*)&h1;
    }
}

// ---------------- launch ----------------
extern "C" void kernel_launch(void* const* d_in, const int* in_sizes, int n_in,
                              void* d_out, int out_size)
{
    const float* x    = (const float*)d_in[0];
    const float* ln1g = (const float*)d_in[1];
    const float* ln1b = (const float*)d_in[2];
    const float* ln2g = (const float*)d_in[3];
    const float* ln2b = (const float*)d_in[4];
    const float* Wq = (const float*)d_in[5];
    const float* bq = (const float*)d_in[6];
    const float* Wk = (const float*)d_in[7];
    const float* bk = (const float*)d_in[8];
    const float* Wv = (const float*)d_in[9];
    const float* bv = (const float*)d_in[10];
    const float* Wo = (const float*)d_in[11];
    const float* bo = (const float*)d_in[12];
    const float* W1 = (const float*)d_in[13];
    const float* b1 = (const float*)d_in[14];
    const float* W2 = (const float*)d_in[15];
    const float* b2 = (const float*)d_in[16];
    float* out = (float*)d_out;

    __half *xnh, *qkvh, *ctxh, *ffh, *wqkvh, *woh, *w1h, *w2h;
    float *x1, *bqkv;
    cudaGetSymbolAddress((void**)&xnh,   g_xnh);
    cudaGetSymbolAddress((void**)&qkvh,  g_qkvh);
    cudaGetSymbolAddress((void**)&ctxh,  g_ctxh);
    cudaGetSymbolAddress((void**)&x1,    g_x1);
    cudaGetSymbolAddress((void**)&ffh,   g_ffh);
    cudaGetSymbolAddress((void**)&wqkvh, g_wqkvh);
    cudaGetSymbolAddress((void**)&woh,   g_woh);
    cudaGetSymbolAddress((void**)&w1h,   g_w1h);
    cudaGetSymbolAddress((void**)&w2h,   g_w2h);
    cudaGetSymbolAddress((void**)&bqkv,  g_bqkv);

    cudaFuncSetAttribute(attn_h, cudaFuncAttributeMaxDynamicSharedMemorySize, ATT_SMEM);
    cudaFuncSetAttribute(gemm_h<false,false,true>,  cudaFuncAttributeMaxDynamicSharedMemorySize, GSM_TOTAL);
    cudaFuncSetAttribute(gemm_h<false,true,false>,  cudaFuncAttributeMaxDynamicSharedMemorySize, GSM_TOTAL);
    cudaFuncSetAttribute(gemm_h<true,false,true>,   cudaFuncAttributeMaxDynamicSharedMemorySize, GSM_TOTAL);

    // ---- parallel preprocessing DAG ----
    // s1: convert_qkv (gates GEMM2)        s2: convert Wo (gates GEMM4)
    // s3: convert W1, W2 (gates GEMM6/7)   main: LN1 (gates GEMM2)
    cudaStream_t s1, s2, s3;
    cudaStreamCreateWithFlags(&s1, cudaStreamNonBlocking);
    cudaStreamCreateWithFlags(&s2, cudaStreamNonBlocking);
    cudaStreamCreateWithFlags(&s3, cudaStreamNonBlocking);
    cudaEvent_t eFork, eQkv, eWo, eW12;
    cudaEventCreateWithFlags(&eFork, cudaEventDisableTiming);
    cudaEventCreateWithFlags(&eQkv,  cudaEventDisableTiming);
    cudaEventCreateWithFlags(&eWo,   cudaEventDisableTiming);
    cudaEventCreateWithFlags(&eW12,  cudaEventDisableTiming);

    cudaEventRecord(eFork, 0);
    cudaStreamWaitEvent(s1, eFork, 0);
    cudaStreamWaitEvent(s2, eFork, 0);
    cudaStreamWaitEvent(s3, eFork, 0);

    convert_qkv<<<512, 256, 0, s1>>>(Wq, Wk, Wv, bqkv, bq, bk, bv, wqkvh);
    cudaEventRecord(eQkv, s1);

    convert_h<<<(D_MODEL*D_MODEL)/4096, 256, 0, s2>>>(Wo, woh);
    cudaEventRecord(eWo, s2);

    convert_h<<<(D_MODEL*D_FF)/4096, 256, 0, s3>>>(W1, w1h);
    convert_h<<<(D_FF*D_MODEL)/4096, 256, 0, s3>>>(W2, w2h);
    cudaEventRecord(eW12, s3);

    // main: LN1 runs concurrently with all converts
    ln_kernel<<<NTOK/8, 256>>>(x, ln1g, ln1b, xnh);

    // 2) qkv = xn @ [Wq|Wk|Wv] + [bq|bk|bv]
    cudaStreamWaitEvent(0, eQkv, 0);
    gemm_h<false,false,true><<<dim3(3*D_MODEL/128, NTOK/128), 128, GSM_TOTAL>>>(
        xnh, wqkvh, bqkv, nullptr, nullptr, qkvh, NTOK, 3*D_MODEL, D_MODEL);
    // 3) ctx = attention(q,k,v)
    attn_h<<<dim3(SEQ/128, BATCH*NHEAD), 256, ATT_SMEM>>>(
        qkvh, qkvh + D_MODEL, qkvh + 2*D_MODEL, ctxh, 3*D_MODEL);

    // 4) x1 = x + ctx @ Wo + bo
    cudaStreamWaitEvent(0, eWo, 0);
    gemm_h<false,true,false><<<dim3(D_MODEL/128, NTOK/128), 128, GSM_TOTAL>>>(
        ctxh, woh, bo, x, x1, nullptr, NTOK, D_MODEL, D_MODEL);
    // 5) xn = LN2(x1)
    ln_kernel<<<NTOK/8, 256>>>(x1, ln2g, ln2b, xnh);

    // 6) ffh = relu(xn @ W1 + b1)
    cudaStreamWaitEvent(0, eW12, 0);
    gemm_h<true,false,true><<<dim3(D_FF/128, NTOK/128), 128, GSM_TOTAL>>>(
        xnh, w1h, b1, nullptr, nullptr, ffh, NTOK, D_FF, D_MODEL);
    // 7) out = x1 + ffh @ W2 + b2
    gemm_h<false,true,false><<<dim3(D_MODEL/128, NTOK/128), 128, GSM_TOTAL>>>(
        ffh, w2h, b2, x1, out, nullptr, NTOK, D_MODEL, D_FF);

    cudaEventDestroy(eFork);
    cudaEventDestroy(eQkv);
    cudaEventDestroy(eWo);
    cudaEventDestroy(eW12);
    cudaStreamDestroy(s1);
    cudaStreamDestroy(s2);
    cudaStreamDestroy(s3);
}

// round 15
// speedup vs baseline: 1.0817x; 1.0601x over previous
#include <cuda_runtime.h>
#include <cuda_fp16.h>
#include <cstdint>

#define D_MODEL 1024
#define D_FF    4096
#define SEQ     2048
#define BATCH   4
#define NTOK    (BATCH*SEQ)   /* 8192 */
#define NHEAD   16
#define DK      64
#define HTOK    (NTOK/2)      /* 4096 rows per chain */

// ---------------- scratch (static device globals; no allocation) ----------------
__device__ __half g_xnh  [(size_t)NTOK*D_MODEL];
__device__ __half g_qkvh [(size_t)NTOK*3*D_MODEL];
__device__ __half g_ctxh [(size_t)NTOK*D_MODEL];
__device__ float  g_x1   [(size_t)NTOK*D_MODEL];
__device__ __half g_ffh  [(size_t)NTOK*D_FF];
__device__ __half g_wqkvh[(size_t)D_MODEL*3*D_MODEL];   // [K=1024][N=3072]
__device__ __half g_woh  [(size_t)D_MODEL*D_MODEL];     // [K][N]
__device__ __half g_w1h  [(size_t)D_MODEL*D_FF];        // [1024][4096]
__device__ __half g_w2h  [(size_t)D_FF*D_MODEL];        // [4096][1024]
__device__ float  g_bqkv [3*D_MODEL];

// ---------------- PTX helpers ----------------
__device__ __forceinline__ uint32_t smem_u32(const void* p) {
    uint32_t a;
    asm("{ .reg .u64 t; cvta.to.shared.u64 t, %1; cvt.u32.u64 %0, t; }"
        : "=r"(a) : "l"(p));
    return a;
}

#define LDSM4(r0, r1, r2, r3, a) \
    asm volatile("ldmatrix.sync.aligned.m8n8.x4.shared.b16 {%0,%1,%2,%3}, [%4];" \
        : "=r"(r0), "=r"(r1), "=r"(r2), "=r"(r3) : "r"(a))
#define LDSM4T(r0, r1, r2, r3, a) \
    asm volatile("ldmatrix.sync.aligned.m8n8.x4.trans.shared.b16 {%0,%1,%2,%3}, [%4];" \
        : "=r"(r0), "=r"(r1), "=r"(r2), "=r"(r3) : "r"(a))

#define CP16(dst, src) \
    asm volatile("cp.async.cg.shared.global [%0], [%1], 16;" :: "r"(dst), "l"(src))
#define CP_COMMIT() asm volatile("cp.async.commit_group;" ::: "memory")
#define CP_WAIT1()  asm volatile("cp.async.wait_group 1;" ::: "memory")
#define CP_WAIT4()  asm volatile("cp.async.wait_group 4;" ::: "memory")

// fp16 MMA, fp32 accum: D(16x8) += A(16x16) @ B(16x8)
__device__ __forceinline__ void mma16(float* d, const uint32_t* a, const uint32_t* b) {
    asm volatile(
        "mma.sync.aligned.m16n8k16.row.col.f32.f16.f16.f32 "
        "{%0,%1,%2,%3}, {%4,%5,%6,%7}, {%8,%9}, {%0,%1,%2,%3};"
        : "+f"(d[0]), "+f"(d[1]), "+f"(d[2]), "+f"(d[3])
        : "r"(a[0]), "r"(a[1]), "r"(a[2]), "r"(a[3]), "r"(b[0]), "r"(b[1]));
}

// ---------------- LayerNorm: warp-per-row, MLP=8, f32 in fp16 out ----------------
__global__ void ln_kernel(const float* __restrict__ x,
                          const float* __restrict__ gamma,
                          const float* __restrict__ beta,
                          __half* __restrict__ y)
{
    const int lane = threadIdx.x & 31;
    const int wrp  = threadIdx.x >> 5;
    const int row  = blockIdx.x * 8 + wrp;

    const float4* xr = (const float4*)(x + (size_t)row * D_MODEL);
    float4 v[8];
    #pragma unroll
    for (int i = 0; i < 8; i++) v[i] = xr[lane + 32 * i];

    float s = 0.f, ss = 0.f;
    #pragma unroll
    for (int i = 0; i < 8; i++) {
        s  += v[i].x + v[i].y + v[i].z + v[i].w;
        ss += v[i].x*v[i].x + v[i].y*v[i].y + v[i].z*v[i].z + v[i].w*v[i].w;
    }
    #pragma unroll
    for (int off = 16; off; off >>= 1) {
        s  += __shfl_xor_sync(0xffffffffu, s,  off);
        ss += __shfl_xor_sync(0xffffffffu, ss, off);
    }
    const float mu   = s * (1.0f / D_MODEL);
    const float var  = ss * (1.0f / D_MODEL) - mu * mu;
    const float rstd = rsqrtf(var + 1e-5f);

    __half* yr = y + (size_t)row * D_MODEL;
    #pragma unroll
    for (int i = 0; i < 8; i++) {
        const int e = lane + 32 * i;
        const float4 g4 = ((const float4*)gamma)[e];
        const float4 b4 = ((const float4*)beta)[e];
        const float ox = (v[i].x - mu) * rstd * g4.x + b4.x;
        const float oy = (v[i].y - mu) * rstd * g4.y + b4.y;
        const float oz = (v[i].z - mu) * rstd * g4.z + b4.z;
        const float ow = (v[i].w - mu) * rstd * g4.w + b4.w;
        __half2 h0 = __floats2half2_rn(ox, oy);
        __half2 h1 = __floats2half2_rn(oz, ow);
        uint2 o; o.x = *(uint32_t*)&h0; o.y = *(uint32_t*)&h1;
        *(uint2*)(yr + e * 4) = o;
    }
}

// ---------------- weight convert: f32 -> f16, 4 float4/thread (MLP=4) ----------------
__global__ void convert_h(const float* __restrict__ in, __half* __restrict__ out)
{
    const size_t b0 = (size_t)blockIdx.x * 4096 + threadIdx.x * 4;
    float4 v[4];
    #pragma unroll
    for (int j = 0; j < 4; j++) v[j] = *(const float4*)(in + b0 + j * 1024);
    #pragma unroll
    for (int j = 0; j < 4; j++) {
        __half2 a = __floats2half2_rn(v[j].x, v[j].y);
        __half2 b = __floats2half2_rn(v[j].z, v[j].w);
        uint2 o; o.x = *(uint32_t*)&a; o.y = *(uint32_t*)&b;
        *(uint2*)(out + b0 + j * 1024) = o;
    }
}

// qkv merge-convert + bias concat
__global__ void convert_qkv(const float* __restrict__ Wq, const float* __restrict__ Wk,
                            const float* __restrict__ Wv, float* __restrict__ bqkv,
                            const float* __restrict__ bq, const float* __restrict__ bk,
                            const float* __restrict__ bv, __half* __restrict__ out)
{
    const int k0 = blockIdx.x * 2;            // grid 512
    const int c  = threadIdx.x;               // 0..255
    const float* srcs[3] = { Wq, Wk, Wv };
    float4 v[2][3];
    #pragma unroll
    for (int r = 0; r < 2; r++)
        #pragma unroll
        for (int j = 0; j < 3; j++)
            v[r][j] = ((const float4*)(srcs[j] + (size_t)(k0 + r) * D_MODEL))[c];
    #pragma unroll
    for (int r = 0; r < 2; r++)
        #pragma unroll
        for (int j = 0; j < 3; j++) {
            __half2 a = __floats2half2_rn(v[r][j].x, v[r][j].y);
            __half2 b = __floats2half2_rn(v[r][j].z, v[r][j].w);
            uint2 o; o.x = *(uint32_t*)&a; o.y = *(uint32_t*)&b;
            *(uint2*)(out + (size_t)(k0 + r) * 3 * D_MODEL + j * D_MODEL + c * 4) = o;
        }
    if (blockIdx.x < 3) {
        const float* src = (blockIdx.x == 0) ? bq : (blockIdx.x == 1) ? bk : bv;
        #pragma unroll
        for (int j = 0; j < 4; j++)
            bqkv[blockIdx.x * 1024 + threadIdx.x + j * 256] = src[threadIdx.x + j * 256];
    }
}

// ---------------- fp16 tensor-core GEMM, 2 CTAs/SM, 6-stage k32 pipeline (R10/R11) ----------------
#define STG_BYTES 16384
#define GSM_TOTAL (6 * STG_BYTES)     /* 98304 */

template<bool RELU, bool RESID, bool HOUT>
__global__ __launch_bounds__(128, 2)
void gemm_h(const __half* __restrict__ Ah, const __half* __restrict__ Bh,
            const float* __restrict__ bias, const float* __restrict__ R,
            float* __restrict__ Cf, __half* __restrict__ Ch, int M, int N, int K)
{
    extern __shared__ char smem[];
    const uint32_t sb = smem_u32(smem);
    const int tid  = threadIdx.x;        // 0..127
    const int lane = tid & 31;
    const int wid  = tid >> 5;           // 0..3
    const int wm   = wid & 1;
    const int wn   = wid >> 1;           // 0..1

    const int m0 = blockIdx.y << 7;
    const int n0 = blockIdx.x << 7;

    const int rlA = lane & 15, clA = lane >> 4;
    const int kV = (lane & 7) + ((lane & 8) ? 8 : 0);
    const int cV = (lane >> 4) & 1;

    float acc[4][8][4];
    #pragma unroll
    for (int mi = 0; mi < 4; mi++)
        #pragma unroll
        for (int ni = 0; ni < 8; ni++)
            #pragma unroll
            for (int c = 0; c < 4; c++) acc[mi][ni][c] = 0.f;

    const int T = K >> 5;

    #define ISSUE_STAGE(s, buf) do { \
        const uint32_t b0_ = sb + (buf) * STG_BYTES; \
        _Pragma("unroll") \
        for (int j = 0; j < 4; j++) { \
            const int c_ = tid + j * 128, row_ = c_ >> 2, ch_ = c_ & 3; \
            CP16(b0_ + row_ * 64 + ((ch_ ^ ((row_ >> 1) & 3)) << 4), \
                 Ah + (size_t)(m0 + row_) * K + (s) * 32 + ch_ * 8); \
        } \
        _Pragma("unroll") \
        for (int j = 0; j < 4; j++) { \
            const int c_ = tid + j * 128, row_ = c_ >> 4, ch_ = c_ & 15; \
            const int ph_ = (ch_ & 8) | ((ch_ & 7) ^ (row_ & 7)); \
            CP16(b0_ + 8192 + row_ * 256 + (ph_ << 4), \
                 Bh + (size_t)((s) * 32 + row_) * N + n0 + ch_ * 8); \
        } \
    } while (0)

    #define LOAD_FRAGS(a_, b_, s_) do { \
        _Pragma("unroll") \
        for (int mi = 0; mi < 4; mi++) { \
            const int row = wm * 64 + mi * 16 + rlA; \
            LDSM4((a_)[mi][0], (a_)[mi][1], (a_)[mi][2], (a_)[mi][3], \
                  sA + row * 64 + (((2 * (s_) + clA) ^ ((row >> 1) & 3)) << 4)); \
        } \
        _Pragma("unroll") \
        for (int bb = 0; bb < 4; bb++) { \
            const int c = wn * 8 + 2 * bb + cV; \
            const int ph = (c & 8) | ((c & 7) ^ (kV & 7)); \
            LDSM4T((b_)[2*bb][0], (b_)[2*bb][1], (b_)[2*bb+1][0], (b_)[2*bb+1][1], \
                   sB + (16 * (s_) + kV) * 256 + (ph << 4)); \
        } \
    } while (0)

    #pragma unroll
    for (int i = 0; i < 5; i++) {
        if (i < T) ISSUE_STAGE(i, i);
        CP_COMMIT();
    }

    uint32_t af[2][4][4], bf[2][8][2];

    int cur = 0;
    for (int kt = 0; kt < T; kt++) {
        CP_WAIT4();
        __syncthreads();
        {
            int nb = cur + 5; if (nb >= 6) nb -= 6;
            if (kt + 5 < T) ISSUE_STAGE(kt + 5, nb);
            CP_COMMIT();
        }
        const uint32_t sA = sb + cur * STG_BYTES;
        const uint32_t sB = sA + 8192;

        LOAD_FRAGS(af[0], bf[0], 0);
        LOAD_FRAGS(af[1], bf[1], 1);
        #pragma unroll
        for (int s = 0; s < 2; s++) {
            #pragma unroll
            for (int mi = 0; mi < 4; mi++)
                #pragma unroll
                for (int ni = 0; ni < 8; ni++)
                    mma16(acc[mi][ni], af[s][mi], bf[s][ni]);
        }
        cur = (cur == 5) ? 0 : cur + 1;
    }
    #undef ISSUE_STAGE
    #undef LOAD_FRAGS

    // ---- epilogue ----
    const int g  = lane >> 2;
    const int t2 = lane & 3;
    #pragma unroll
    for (int ni = 0; ni < 8; ni++) {
        const int c = n0 + wn * 64 + ni * 8 + 2 * t2;
        const float2 bi = *(const float2*)&bias[c];
        #pragma unroll
        for (int mi = 0; mi < 4; mi++) {
            const int r0 = m0 + wm * 64 + mi * 16 + g;
            #pragma unroll
            for (int h = 0; h < 2; h++) {
                const int rr = r0 + h * 8;
                float vx = acc[mi][ni][2 * h]     + bi.x;
                float vy = acc[mi][ni][2 * h + 1] + bi.y;
                if (RELU) { vx = fmaxf(vx, 0.f); vy = fmaxf(vy, 0.f); }
                const size_t idx = (size_t)rr * N + c;
                if (RESID) {
                    const float2 rs = *(const float2*)&R[idx];
                    vx += rs.x; vy += rs.y;
                }
                if (HOUT) {
                    __half2 hv = __floats2half2_rn(vx, vy);
                    *(uint32_t*)&Ch[idx] = *(uint32_t*)&hv;
                } else {
                    float2 o; o.x = vx; o.y = vy;
                    *(float2*)&Cf[idx] = o;
                }
            }
        }
    }
}

// ---------------- fp16 flash attention, register-resident P, 2 CTAs/SM (R11) ----------------
#define ATT_STG  16384
#define ATT_SMEM (16384 + 3 * ATT_STG)   /* 65536 */

__global__ __launch_bounds__(256, 2)
void attn_h(const __half* __restrict__ Qg, const __half* __restrict__ Kg,
            const __half* __restrict__ Vg, __half* __restrict__ O, int ld)
{
    extern __shared__ char smem[];
    const uint32_t sb = smem_u32(smem);
    const int tid  = threadIdx.x;
    const int lane = tid & 31;
    const int wid  = tid >> 5;
    const int g    = lane >> 2;
    const int t    = lane & 3;
    const int swz  = lane & 7;

    const int bh = blockIdx.y;
    const int b  = bh >> 4;
    const int h  = bh & 15;
    const int q0 = blockIdx.x << 7;

    const size_t base  = (size_t)b * SEQ * ld + (size_t)h * DK;
    const size_t obase = (size_t)b * SEQ * D_MODEL + (size_t)h * DK;

    #pragma unroll
    for (int p = 0; p < 4; p++) {
        const int c = tid + p * 256, row = c >> 3, ch = c & 7;
        *(uint4*)(smem + row * 128 + ((ch ^ (row & 7)) << 4)) =
            *(const uint4*)(Qg + base + (size_t)(q0 + row) * ld + ch * 8);
    }
    __syncthreads();

    uint32_t aq[4][4];
    {
        const int rowA = wid * 16 + (lane & 15);
        const int clA  = lane >> 4;
        #pragma unroll
        for (int kb = 0; kb < 4; kb++)
            LDSM4(aq[kb][0], aq[kb][1], aq[kb][2], aq[kb][3],
                  sb + rowA * 128 + (((2 * kb + clA) ^ swz) << 4));
    }

    const int rlB = (lane & 7) + ((lane >> 4) << 3);
    const int clB = (lane >> 3) & 1;
    const int kV  = (lane & 7) + ((lane & 8) ? 8 : 0);
    const int cV  = (lane >> 4) & 1;

    float m0v = -1e30f, m1v = -1e30f, l0 = 0.f, l1 = 0.f;
    float oacc[8][4];
    #pragma unroll
    for (int ni = 0; ni < 8; ni++)
        #pragma unroll
        for (int c = 0; c < 4; c++) oacc[ni][c] = 0.f;

    #define ISSUE_KV(s, buf) do { \
        const uint32_t kb_ = sb + 16384 + (buf) * ATT_STG; \
        _Pragma("unroll") \
        for (int j = 0; j < 2; j++) { \
            const int c_ = tid + j * 256, row_ = c_ >> 3, ch_ = c_ & 7; \
            const uint32_t off_ = row_ * 128 + ((ch_ ^ (row_ & 7)) << 4); \
            const size_t gsrc = base + (size_t)((s) * 64 + row_) * ld + ch_ * 8; \
            CP16(kb_ + off_,        Kg + gsrc); \
            CP16(kb_ + 8192 + off_, Vg + gsrc); \
        } \
    } while (0)

    ISSUE_KV(0, 0); CP_COMMIT();
    ISSUE_KV(1, 1); CP_COMMIT();

    int cur = 0;
    const int T = SEQ / 64;
    for (int kt = 0; kt < T; kt++) {
        CP_WAIT1();
        __syncthreads();
        {
            int nb = cur + 2; if (nb >= 3) nb -= 3;
            if (kt + 2 < T) ISSUE_KV(kt + 2, nb);
            CP_COMMIT();
        }
        const uint32_t kbuf = sb + 16384 + cur * ATT_STG;
        const uint32_t vbuf = kbuf + 8192;

        float sacc[8][4];
        #pragma unroll
        for (int ni = 0; ni < 8; ni++)
            #pragma unroll
            for (int c = 0; c < 4; c++) sacc[ni][c] = 0.f;

        #pragma unroll
        for (int kb = 0; kb < 4; kb++) {
            uint32_t bf[8][2];
            #pragma unroll
            for (int a = 0; a < 4; a++) {
                const int row = 16 * a + rlB;
                LDSM4(bf[2*a][0], bf[2*a][1], bf[2*a+1][0], bf[2*a+1][1],
                      kbuf + row * 128 + (((2 * kb + clB) ^ swz) << 4));
            }
            #pragma unroll
            for (int ni = 0; ni < 8; ni++)
                mma16(sacc[ni], aq[kb], bf[ni]);
        }

        #pragma unroll
        for (int ni = 0; ni < 8; ni++) {
            sacc[ni][0] *= 0.125f; sacc[ni][1] *= 0.125f;
            sacc[ni][2] *= 0.125f; sacc[ni][3] *= 0.125f;
        }
        float mx0 = -1e30f, mx1 = -1e30f;
        #pragma unroll
        for (int ni = 0; ni < 8; ni++) {
            mx0 = fmaxf(mx0, fmaxf(sacc[ni][0], sacc[ni][1]));
            mx1 = fmaxf(mx1, fmaxf(sacc[ni][2], sacc[ni][3]));
        }
        mx0 = fmaxf(mx0, __shfl_xor_sync(0xffffffffu, mx0, 1));
        mx0 = fmaxf(mx0, __shfl_xor_sync(0xffffffffu, mx0, 2));
        mx1 = fmaxf(mx1, __shfl_xor_sync(0xffffffffu, mx1, 1));
        mx1 = fmaxf(mx1, __shfl_xor_sync(0xffffffffu, mx1, 2));

        const float mn0 = fmaxf(m0v, mx0);
        const float mn1 = fmaxf(m1v, mx1);
        const float al0 = __expf(m0v - mn0);
        const float al1 = __expf(m1v - mn1);
        m0v = mn0; m1v = mn1;

        uint32_t pa[8][2];
        float sum0 = 0.f, sum1 = 0.f;
        #pragma unroll
        for (int ni = 0; ni < 8; ni++) {
            const float p0 = __expf(sacc[ni][0] - mn0);
            const float p1 = __expf(sacc[ni][1] - mn0);
            const float p2 = __expf(sacc[ni][2] - mn1);
            const float p3 = __expf(sacc[ni][3] - mn1);
            sum0 += p0 + p1; sum1 += p2 + p3;
            __half2 h0 = __floats2half2_rn(p0, p1);
            __half2 h1 = __floats2half2_rn(p2, p3);
            pa[ni][0] = *(uint32_t*)&h0;
            pa[ni][1] = *(uint32_t*)&h1;
        }
        sum0 += __shfl_xor_sync(0xffffffffu, sum0, 1);
        sum0 += __shfl_xor_sync(0xffffffffu, sum0, 2);
        sum1 += __shfl_xor_sync(0xffffffffu, sum1, 1);
        sum1 += __shfl_xor_sync(0xffffffffu, sum1, 2);
        l0 = l0 * al0 + sum0;
        l1 = l1 * al1 + sum1;

        #pragma unroll
        for (int ni = 0; ni < 8; ni++) {
            oacc[ni][0] *= al0; oacc[ni][1] *= al0;
            oacc[ni][2] *= al1; oacc[ni][3] *= al1;
        }

        #pragma unroll
        for (int kk = 0; kk < 4; kk++) {
            uint32_t bv[8][2];
            #pragma unroll
            for (int bb = 0; bb < 4; bb++) {
                const int key = 16 * kk + kV;
                LDSM4T(bv[2*bb][0], bv[2*bb][1], bv[2*bb+1][0], bv[2*bb+1][1],
                       vbuf + key * 128 + (((2 * bb + cV) ^ swz) << 4));
            }
            uint32_t ap[4] = { pa[2*kk][0], pa[2*kk][1], pa[2*kk+1][0], pa[2*kk+1][1] };
            #pragma unroll
            for (int ni = 0; ni < 8; ni++)
                mma16(oacc[ni], ap, bv[ni]);
        }

        cur = (cur == 2) ? 0 : cur + 1;
    }
    #undef ISSUE_KV

    const float inv0 = 1.f / l0;
    const float inv1 = 1.f / l1;
    const size_t row0 = obase + (size_t)(q0 + wid * 16 + g) * D_MODEL;
    const size_t row1 = row0 + (size_t)8 * D_MODEL;
    #pragma unroll
    for (int ni = 0; ni < 8; ni++) {
        const int c = ni * 8 + 2 * t;
        __half2 h0 = __floats2half2_rn(oacc[ni][0] * inv0, oacc[ni][1] * inv0);
        __half2 h1 = __floats2half2_rn(oacc[ni][2] * inv1, oacc[ni][3] * inv1);
        *(uint32_t*)&O[row0 + c] = *(uint32_t*)&h0;
        *(uint32_t*)&O[row1 + c] = *(uint32_t*)&h1;
    }
}

// ---------------- launch: two batch-split chains on parallel streams ----------------
extern "C" void kernel_launch(void* const* d_in, const int* in_sizes, int n_in,
                              void* d_out, int out_size)
{
    const float* x    = (const float*)d_in[0];
    const float* ln1g = (const float*)d_in[1];
    const float* ln1b = (const float*)d_in[2];
    const float* ln2g = (const float*)d_in[3];
    const float* ln2b = (const float*)d_in[4];
    const float* Wq = (const float*)d_in[5];
    const float* bq = (const float*)d_in[6];
    const float* Wk = (const float*)d_in[7];
    const float* bk = (const float*)d_in[8];
    const float* Wv = (const float*)d_in[9];
    const float* bv = (const float*)d_in[10];
    const float* Wo = (const float*)d_in[11];
    const float* bo = (const float*)d_in[12];
    const float* W1 = (const float*)d_in[13];
    const float* b1 = (const float*)d_in[14];
    const float* W2 = (const float*)d_in[15];
    const float* b2 = (const float*)d_in[16];
    float* out = (float*)d_out;

    __half *xnh, *qkvh, *ctxh, *ffh, *wqkvh, *woh, *w1h, *w2h;
    float *x1, *bqkv;
    cudaGetSymbolAddress((void**)&xnh,   g_xnh);
    cudaGetSymbolAddress((void**)&qkvh,  g_qkvh);
    cudaGetSymbolAddress((void**)&ctxh,  g_ctxh);
    cudaGetSymbolAddress((void**)&x1,    g_x1);
    cudaGetSymbolAddress((void**)&ffh,   g_ffh);
    cudaGetSymbolAddress((void**)&wqkvh, g_wqkvh);
    cudaGetSymbolAddress((void**)&woh,   g_woh);
    cudaGetSymbolAddress((void**)&w1h,   g_w1h);
    cudaGetSymbolAddress((void**)&w2h,   g_w2h);
    cudaGetSymbolAddress((void**)&bqkv,  g_bqkv);

    cudaFuncSetAttribute(attn_h, cudaFuncAttributeMaxDynamicSharedMemorySize, ATT_SMEM);
    cudaFuncSetAttribute(gemm_h<false,false,true>,  cudaFuncAttributeMaxDynamicSharedMemorySize, GSM_TOTAL);
    cudaFuncSetAttribute(gemm_h<false,true,false>,  cudaFuncAttributeMaxDynamicSharedMemorySize, GSM_TOTAL);
    cudaFuncSetAttribute(gemm_h<true,false,true>,   cudaFuncAttributeMaxDynamicSharedMemorySize, GSM_TOTAL);

    cudaStream_t s1, s2, s3, sB;
    cudaStreamCreateWithFlags(&s1, cudaStreamNonBlocking);
    cudaStreamCreateWithFlags(&s2, cudaStreamNonBlocking);
    cudaStreamCreateWithFlags(&s3, cudaStreamNonBlocking);
    cudaStreamCreateWithFlags(&sB, cudaStreamNonBlocking);
    cudaEvent_t eFork, eQkv, eWo, eW12, eDoneB;
    cudaEventCreateWithFlags(&eFork,  cudaEventDisableTiming);
    cudaEventCreateWithFlags(&eQkv,   cudaEventDisableTiming);
    cudaEventCreateWithFlags(&eWo,    cudaEventDisableTiming);
    cudaEventCreateWithFlags(&eW12,   cudaEventDisableTiming);
    cudaEventCreateWithFlags(&eDoneB, cudaEventDisableTiming);

    cudaEventRecord(eFork, 0);
    cudaStreamWaitEvent(s1, eFork, 0);
    cudaStreamWaitEvent(s2, eFork, 0);
    cudaStreamWaitEvent(s3, eFork, 0);
    cudaStreamWaitEvent(sB, eFork, 0);

    // weight preprocessing (shared by both chains)
    convert_qkv<<<512, 256, 0, s1>>>(Wq, Wk, Wv, bqkv, bq, bk, bv, wqkvh);
    cudaEventRecord(eQkv, s1);
    convert_h<<<(D_MODEL*D_MODEL)/4096, 256, 0, s2>>>(Wo, woh);
    cudaEventRecord(eWo, s2);
    convert_h<<<(D_MODEL*D_FF)/4096, 256, 0, s3>>>(W1, w1h);
    convert_h<<<(D_FF*D_MODEL)/4096, 256, 0, s3>>>(W2, w2h);
    cudaEventRecord(eW12, s3);

    // per-half chain macro: stream S, token offset R (0 or HTOK)
    #define CHAIN(S, R) do { \
        const size_t rD  = (size_t)(R) * D_MODEL; \
        const size_t r3D = (size_t)(R) * 3 * D_MODEL; \
        const size_t rF  = (size_t)(R) * D_FF; \
        ln_kernel<<<HTOK/8, 256, 0, (S)>>>(x + rD, ln1g, ln1b, xnh + rD); \
        cudaStreamWaitEvent((S), eQkv, 0); \
        gemm_h<false,false,true><<<dim3(3*D_MODEL/128, HTOK/128), 128, GSM_TOTAL, (S)>>>( \
            xnh + rD, wqkvh, bqkv, nullptr, nullptr, qkvh + r3D, HTOK, 3*D_MODEL, D_MODEL); \
        attn_h<<<dim3(SEQ/128, (BATCH/2)*NHEAD), 256, ATT_SMEM, (S)>>>( \
            qkvh + r3D, qkvh + r3D + D_MODEL, qkvh + r3D + 2*D_MODEL, ctxh + rD, 3*D_MODEL); \
        cudaStreamWaitEvent((S), eWo, 0); \
        gemm_h<false,true,false><<<dim3(D_MODEL/128, HTOK/128), 128, GSM_TOTAL, (S)>>>( \
            ctxh + rD, woh, bo, x + rD, x1 + rD, nullptr, HTOK, D_MODEL, D_MODEL); \
        ln_kernel<<<HTOK/8, 256, 0, (S)>>>(x1 + rD, ln2g, ln2b, xnh + rD); \
        cudaStreamWaitEvent((S), eW12, 0); \
        gemm_h<true,false,true><<<dim3(D_FF/128, HTOK/128), 128, GSM_TOTAL, (S)>>>( \
            xnh + rD, w1h, b1, nullptr, nullptr, ffh + rF, HTOK, D_FF, D_MODEL); \
        gemm_h<false,true,false><<<dim3(D_MODEL/128, HTOK/128), 128, GSM_TOTAL, (S)>>>( \
            ffh + rF, w2h, b2, x1 + rD, out + rD, nullptr, HTOK, D_MODEL, D_FF); \
    } while (0)

    CHAIN(sB, HTOK);     // second half on side stream
    CHAIN(0,  0);        // first half on main (capture) stream
    #undef CHAIN

    // join: main stream must observe chain-B completion
    cudaEventRecord(eDoneB, sB);
    cudaStreamWaitEvent(0, eDoneB, 0);

    cudaEventDestroy(eFork);
    cudaEventDestroy(eQkv);
    cudaEventDestroy(eWo);
    cudaEventDestroy(eW12);
    cudaEventDestroy(eDoneB);
    cudaStreamDestroy(s1);
    cudaStreamDestroy(s2);
    cudaStreamDestroy(s3);
    cudaStreamDestroy(sB);
}

// round 17
// speedup vs baseline: 1.1018x; 1.0186x over previous
#include <cuda_runtime.h>
#include <cuda_fp16.h>
#include <cstdint>

#define D_MODEL 1024
#define D_FF    4096
#define SEQ     2048
#define BATCH   4
#define NTOK    (BATCH*SEQ)   /* 8192 */
#define NHEAD   16
#define DK      64
#define QTOK    (NTOK/4)      /* 2048 rows per chain */

// ---------------- scratch (static device globals; no allocation) ----------------
__device__ __half g_xnh  [(size_t)NTOK*D_MODEL];
__device__ __half g_qkvh [(size_t)NTOK*3*D_MODEL];
__device__ __half g_ctxh [(size_t)NTOK*D_MODEL];
__device__ float  g_x1   [(size_t)NTOK*D_MODEL];
__device__ __half g_ffh  [(size_t)NTOK*D_FF];
__device__ __half g_wqkvh[(size_t)D_MODEL*3*D_MODEL];   // [K=1024][N=3072]
__device__ __half g_woh  [(size_t)D_MODEL*D_MODEL];     // [K][N]
__device__ __half g_w1h  [(size_t)D_MODEL*D_FF];        // [1024][4096]
__device__ __half g_w2h  [(size_t)D_FF*D_MODEL];        // [4096][1024]
__device__ float  g_bqkv [3*D_MODEL];

// ---------------- PTX helpers ----------------
__device__ __forceinline__ uint32_t smem_u32(const void* p) {
    uint32_t a;
    asm("{ .reg .u64 t; cvta.to.shared.u64 t, %1; cvt.u32.u64 %0, t; }"
        : "=r"(a) : "l"(p));
    return a;
}

#define LDSM4(r0, r1, r2, r3, a) \
    asm volatile("ldmatrix.sync.aligned.m8n8.x4.shared.b16 {%0,%1,%2,%3}, [%4];" \
        : "=r"(r0), "=r"(r1), "=r"(r2), "=r"(r3) : "r"(a))
#define LDSM4T(r0, r1, r2, r3, a) \
    asm volatile("ldmatrix.sync.aligned.m8n8.x4.trans.shared.b16 {%0,%1,%2,%3}, [%4];" \
        : "=r"(r0), "=r"(r1), "=r"(r2), "=r"(r3) : "r"(a))

#define CP16(dst, src) \
    asm volatile("cp.async.cg.shared.global [%0], [%1], 16;" :: "r"(dst), "l"(src))
#define CP_COMMIT() asm volatile("cp.async.commit_group;" ::: "memory")
#define CP_WAIT1()  asm volatile("cp.async.wait_group 1;" ::: "memory")
#define CP_WAIT4()  asm volatile("cp.async.wait_group 4;" ::: "memory")

// fp16 MMA, fp32 accum: D(16x8) += A(16x16) @ B(16x8)
__device__ __forceinline__ void mma16(float* d, const uint32_t* a, const uint32_t* b) {
    asm volatile(
        "mma.sync.aligned.m16n8k16.row.col.f32.f16.f16.f32 "
        "{%0,%1,%2,%3}, {%4,%5,%6,%7}, {%8,%9}, {%0,%1,%2,%3};"
        : "+f"(d[0]), "+f"(d[1]), "+f"(d[2]), "+f"(d[3])
        : "r"(a[0]), "r"(a[1]), "r"(a[2]), "r"(a[3]), "r"(b[0]), "r"(b[1]));
}

// ---------------- LayerNorm: warp-per-row, MLP=8, f32 in fp16 out ----------------
__global__ void ln_kernel(const float* __restrict__ x,
                          const float* __restrict__ gamma,
                          const float* __restrict__ beta,
                          __half* __restrict__ y)
{
    const int lane = threadIdx.x & 31;
    const int wrp  = threadIdx.x >> 5;
    const int row  = blockIdx.x * 8 + wrp;

    const float4* xr = (const float4*)(x + (size_t)row * D_MODEL);
    float4 v[8];
    #pragma unroll
    for (int i = 0; i < 8; i++) v[i] = xr[lane + 32 * i];

    float s = 0.f, ss = 0.f;
    #pragma unroll
    for (int i = 0; i < 8; i++) {
        s  += v[i].x + v[i].y + v[i].z + v[i].w;
        ss += v[i].x*v[i].x + v[i].y*v[i].y + v[i].z*v[i].z + v[i].w*v[i].w;
    }
    #pragma unroll
    for (int off = 16; off; off >>= 1) {
        s  += __shfl_xor_sync(0xffffffffu, s,  off);
        ss += __shfl_xor_sync(0xffffffffu, ss, off);
    }
    const float mu   = s * (1.0f / D_MODEL);
    const float var  = ss * (1.0f / D_MODEL) - mu * mu;
    const float rstd = rsqrtf(var + 1e-5f);

    __half* yr = y + (size_t)row * D_MODEL;
    #pragma unroll
    for (int i = 0; i < 8; i++) {
        const int e = lane + 32 * i;
        const float4 g4 = ((const float4*)gamma)[e];
        const float4 b4 = ((const float4*)beta)[e];
        const float ox = (v[i].x - mu) * rstd * g4.x + b4.x;
        const float oy = (v[i].y - mu) * rstd * g4.y + b4.y;
        const float oz = (v[i].z - mu) * rstd * g4.z + b4.z;
        const float ow = (v[i].w - mu) * rstd * g4.w + b4.w;
        __half2 h0 = __floats2half2_rn(ox, oy);
        __half2 h1 = __floats2half2_rn(oz, ow);
        uint2 o; o.x = *(uint32_t*)&h0; o.y = *(uint32_t*)&h1;
        *(uint2*)(yr + e * 4) = o;
    }
}

// ---------------- weight convert: f32 -> f16, 4 float4/thread (MLP=4) ----------------
__global__ void convert_h(const float* __restrict__ in, __half* __restrict__ out)
{
    const size_t b0 = (size_t)blockIdx.x * 4096 + threadIdx.x * 4;
    float4 v[4];
    #pragma unroll
    for (int j = 0; j < 4; j++) v[j] = *(const float4*)(in + b0 + j * 1024);
    #pragma unroll
    for (int j = 0; j < 4; j++) {
        __half2 a = __floats2half2_rn(v[j].x, v[j].y);
        __half2 b = __floats2half2_rn(v[j].z, v[j].w);
        uint2 o; o.x = *(uint32_t*)&a; o.y = *(uint32_t*)&b;
        *(uint2*)(out + b0 + j * 1024) = o;
    }
}

// qkv merge-convert + bias concat
__global__ void convert_qkv(const float* __restrict__ Wq, const float* __restrict__ Wk,
                            const float* __restrict__ Wv, float* __restrict__ bqkv,
                            const float* __restrict__ bq, const float* __restrict__ bk,
                            const float* __restrict__ bv, __half* __restrict__ out)
{
    const int k0 = blockIdx.x * 2;            // grid 512
    const int c  = threadIdx.x;               // 0..255
    const float* srcs[3] = { Wq, Wk, Wv };
    float4 v[2][3];
    #pragma unroll
    for (int r = 0; r < 2; r++)
        #pragma unroll
        for (int j = 0; j < 3; j++)
            v[r][j] = ((const float4*)(srcs[j] + (size_t)(k0 + r) * D_MODEL))[c];
    #pragma unroll
    for (int r = 0; r < 2; r++)
        #pragma unroll
        for (int j = 0; j < 3; j++) {
            __half2 a = __floats2half2_rn(v[r][j].x, v[r][j].y);
            __half2 b = __floats2half2_rn(v[r][j].z, v[r][j].w);
            uint2 o; o.x = *(uint32_t*)&a; o.y = *(uint32_t*)&b;
            *(uint2*)(out + (size_t)(k0 + r) * 3 * D_MODEL + j * D_MODEL + c * 4) = o;
        }
    if (blockIdx.x < 3) {
        const float* src = (blockIdx.x == 0) ? bq : (blockIdx.x == 1) ? bk : bv;
        #pragma unroll
        for (int j = 0; j < 4; j++)
            bqkv[blockIdx.x * 1024 + threadIdx.x + j * 256] = src[threadIdx.x + j * 256];
    }
}

// ---------------- fp16 tensor-core GEMM, 2 CTAs/SM, 6-stage k32 pipeline ----------------
#define STG_BYTES 16384
#define GSM_TOTAL (6 * STG_BYTES)     /* 98304 */

template<bool RELU, bool RESID, bool HOUT>
__global__ __launch_bounds__(128, 2)
void gemm_h(const __half* __restrict__ Ah, const __half* __restrict__ Bh,
            const float* __restrict__ bias, const float* __restrict__ R,
            float* __restrict__ Cf, __half* __restrict__ Ch, int M, int N, int K)
{
    extern __shared__ char smem[];
    const uint32_t sb = smem_u32(smem);
    const int tid  = threadIdx.x;        // 0..127
    const int lane = tid & 31;
    const int wid  = tid >> 5;           // 0..3
    const int wm   = wid & 1;
    const int wn   = wid >> 1;           // 0..1

    const int m0 = blockIdx.y << 7;
    const int n0 = blockIdx.x << 7;

    const int rlA = lane & 15, clA = lane >> 4;
    const int kV = (lane & 7) + ((lane & 8) ? 8 : 0);
    const int cV = (lane >> 4) & 1;

    float acc[4][8][4];
    #pragma unroll
    for (int mi = 0; mi < 4; mi++)
        #pragma unroll
        for (int ni = 0; ni < 8; ni++)
            #pragma unroll
            for (int c = 0; c < 4; c++) acc[mi][ni][c] = 0.f;

    const int T = K >> 5;

    #define ISSUE_STAGE(s, buf) do { \
        const uint32_t b0_ = sb + (buf) * STG_BYTES; \
        _Pragma("unroll") \
        for (int j = 0; j < 4; j++) { \
            const int c_ = tid + j * 128, row_ = c_ >> 2, ch_ = c_ & 3; \
            CP16(b0_ + row_ * 64 + ((ch_ ^ ((row_ >> 1) & 3)) << 4), \
                 Ah + (size_t)(m0 + row_) * K + (s) * 32 + ch_ * 8); \
        } \
        _Pragma("unroll") \
        for (int j = 0; j < 4; j++) { \
            const int c_ = tid + j * 128, row_ = c_ >> 4, ch_ = c_ & 15; \
            const int ph_ = (ch_ & 8) | ((ch_ & 7) ^ (row_ & 7)); \
            CP16(b0_ + 8192 + row_ * 256 + (ph_ << 4), \
                 Bh + (size_t)((s) * 32 + row_) * N + n0 + ch_ * 8); \
        } \
    } while (0)

    #define LOAD_FRAGS(a_, b_, s_) do { \
        _Pragma("unroll") \
        for (int mi = 0; mi < 4; mi++) { \
            const int row = wm * 64 + mi * 16 + rlA; \
            LDSM4((a_)[mi][0], (a_)[mi][1], (a_)[mi][2], (a_)[mi][3], \
                  sA + row * 64 + (((2 * (s_) + clA) ^ ((row >> 1) & 3)) << 4)); \
        } \
        _Pragma("unroll") \
        for (int bb = 0; bb < 4; bb++) { \
            const int c = wn * 8 + 2 * bb + cV; \
            const int ph = (c & 8) | ((c & 7) ^ (kV & 7)); \
            LDSM4T((b_)[2*bb][0], (b_)[2*bb][1], (b_)[2*bb+1][0], (b_)[2*bb+1][1], \
                   sB + (16 * (s_) + kV) * 256 + (ph << 4)); \
        } \
    } while (0)

    #pragma unroll
    for (int i = 0; i < 5; i++) {
        if (i < T) ISSUE_STAGE(i, i);
        CP_COMMIT();
    }

    uint32_t af[2][4][4], bf[2][8][2];

    int cur = 0;
    for (int kt = 0; kt < T; kt++) {
        CP_WAIT4();
        __syncthreads();
        {
            int nb = cur + 5; if (nb >= 6) nb -= 6;
            if (kt + 5 < T) ISSUE_STAGE(kt + 5, nb);
            CP_COMMIT();
        }
        const uint32_t sA = sb + cur * STG_BYTES;
        const uint32_t sB = sA + 8192;

        LOAD_FRAGS(af[0], bf[0], 0);
        LOAD_FRAGS(af[1], bf[1], 1);
        #pragma unroll
        for (int s = 0; s < 2; s++) {
            #pragma unroll
            for (int mi = 0; mi < 4; mi++)
                #pragma unroll
                for (int ni = 0; ni < 8; ni++)
                    mma16(acc[mi][ni], af[s][mi], bf[s][ni]);
        }
        cur = (cur == 5) ? 0 : cur + 1;
    }
    #undef ISSUE_STAGE
    #undef LOAD_FRAGS

    // ---- epilogue ----
    const int g  = lane >> 2;
    const int t2 = lane & 3;
    #pragma unroll
    for (int ni = 0; ni < 8; ni++) {
        const int c = n0 + wn * 64 + ni * 8 + 2 * t2;
        const float2 bi = *(const float2*)&bias[c];
        #pragma unroll
        for (int mi = 0; mi < 4; mi++) {
            const int r0 = m0 + wm * 64 + mi * 16 + g;
            #pragma unroll
            for (int h = 0; h < 2; h++) {
                const int rr = r0 + h * 8;
                float vx = acc[mi][ni][2 * h]     + bi.x;
                float vy = acc[mi][ni][2 * h + 1] + bi.y;
                if (RELU) { vx = fmaxf(vx, 0.f); vy = fmaxf(vy, 0.f); }
                const size_t idx = (size_t)rr * N + c;
                if (RESID) {
                    const float2 rs = *(const float2*)&R[idx];
                    vx += rs.x; vy += rs.y;
                }
                if (HOUT) {
                    __half2 hv = __floats2half2_rn(vx, vy);
                    *(uint32_t*)&Ch[idx] = *(uint32_t*)&hv;
                } else {
                    float2 o; o.x = vx; o.y = vy;
                    *(float2*)&Cf[idx] = o;
                }
            }
        }
    }
}

// ---------------- fp16 flash attention, register-resident P, 2 CTAs/SM ----------------
#define ATT_STG  16384
#define ATT_SMEM (16384 + 3 * ATT_STG)   /* 65536 */

__global__ __launch_bounds__(256, 2)
void attn_h(const __half* __restrict__ Qg, const __half* __restrict__ Kg,
            const __half* __restrict__ Vg, __half* __restrict__ O, int ld)
{
    extern __shared__ char smem[];
    const uint32_t sb = smem_u32(smem);
    const int tid  = threadIdx.x;
    const int lane = tid & 31;
    const int wid  = tid >> 5;
    const int g    = lane >> 2;
    const int t    = lane & 3;
    const int swz  = lane & 7;

    const int bh = blockIdx.y;
    const int b  = bh >> 4;
    const int h  = bh & 15;
    const int q0 = blockIdx.x << 7;

    const size_t base  = (size_t)b * SEQ * ld + (size_t)h * DK;
    const size_t obase = (size_t)b * SEQ * D_MODEL + (size_t)h * DK;

    #pragma unroll
    for (int p = 0; p < 4; p++) {
        const int c = tid + p * 256, row = c >> 3, ch = c & 7;
        *(uint4*)(smem + row * 128 + ((ch ^ (row & 7)) << 4)) =
            *(const uint4*)(Qg + base + (size_t)(q0 + row) * ld + ch * 8);
    }
    __syncthreads();

    uint32_t aq[4][4];
    {
        const int rowA = wid * 16 + (lane & 15);
        const int clA  = lane >> 4;
        #pragma unroll
        for (int kb = 0; kb < 4; kb++)
            LDSM4(aq[kb][0], aq[kb][1], aq[kb][2], aq[kb][3],
                  sb + rowA * 128 + (((2 * kb + clA) ^ swz) << 4));
    }

    const int rlB = (lane & 7) + ((lane >> 4) << 3);
    const int clB = (lane >> 3) & 1;
    const int kV  = (lane & 7) + ((lane & 8) ? 8 : 0);
    const int cV  = (lane >> 4) & 1;

    float m0v = -1e30f, m1v = -1e30f, l0 = 0.f, l1 = 0.f;
    float oacc[8][4];
    #pragma unroll
    for (int ni = 0; ni < 8; ni++)
        #pragma unroll
        for (int c = 0; c < 4; c++) oacc[ni][c] = 0.f;

    #define ISSUE_KV(s, buf) do { \
        const uint32_t kb_ = sb + 16384 + (buf) * ATT_STG; \
        _Pragma("unroll") \
        for (int j = 0; j < 2; j++) { \
            const int c_ = tid + j * 256, row_ = c_ >> 3, ch_ = c_ & 7; \
            const uint32_t off_ = row_ * 128 + ((ch_ ^ (row_ & 7)) << 4); \
            const size_t gsrc = base + (size_t)((s) * 64 + row_) * ld + ch_ * 8; \
            CP16(kb_ + off_,        Kg + gsrc); \
            CP16(kb_ + 8192 + off_, Vg + gsrc); \
        } \
    } while (0)

    ISSUE_KV(0, 0); CP_COMMIT();
    ISSUE_KV(1, 1); CP_COMMIT();

    int cur = 0;
    const int T = SEQ / 64;
    for (int kt = 0; kt < T; kt++) {
        CP_WAIT1();
        __syncthreads();
        {
            int nb = cur + 2; if (nb >= 3) nb -= 3;
            if (kt + 2 < T) ISSUE_KV(kt + 2, nb);
            CP_COMMIT();
        }
        const uint32_t kbuf = sb + 16384 + cur * ATT_STG;
        const uint32_t vbuf = kbuf + 8192;

        float sacc[8][4];
        #pragma unroll
        for (int ni = 0; ni < 8; ni++)
            #pragma unroll
            for (int c = 0; c < 4; c++) sacc[ni][c] = 0.f;

        #pragma unroll
        for (int kb = 0; kb < 4; kb++) {
            uint32_t bf[8][2];
            #pragma unroll
            for (int a = 0; a < 4; a++) {
                const int row = 16 * a + rlB;
                LDSM4(bf[2*a][0], bf[2*a][1], bf[2*a+1][0], bf[2*a+1][1],
                      kbuf + row * 128 + (((2 * kb + clB) ^ swz) << 4));
            }
            #pragma unroll
            for (int ni = 0; ni < 8; ni++)
                mma16(sacc[ni], aq[kb], bf[ni]);
        }

        #pragma unroll
        for (int ni = 0; ni < 8; ni++) {
            sacc[ni][0] *= 0.125f; sacc[ni][1] *= 0.125f;
            sacc[ni][2] *= 0.125f; sacc[ni][3] *= 0.125f;
        }
        float mx0 = -1e30f, mx1 = -1e30f;
        #pragma unroll
        for (int ni = 0; ni < 8; ni++) {
            mx0 = fmaxf(mx0, fmaxf(sacc[ni][0], sacc[ni][1]));
            mx1 = fmaxf(mx1, fmaxf(sacc[ni][2], sacc[ni][3]));
        }
        mx0 = fmaxf(mx0, __shfl_xor_sync(0xffffffffu, mx0, 1));
        mx0 = fmaxf(mx0, __shfl_xor_sync(0xffffffffu, mx0, 2));
        mx1 = fmaxf(mx1, __shfl_xor_sync(0xffffffffu, mx1, 1));
        mx1 = fmaxf(mx1, __shfl_xor_sync(0xffffffffu, mx1, 2));

        const float mn0 = fmaxf(m0v, mx0);
        const float mn1 = fmaxf(m1v, mx1);
        const float al0 = __expf(m0v - mn0);
        const float al1 = __expf(m1v - mn1);
        m0v = mn0; m1v = mn1;

        uint32_t pa[8][2];
        float sum0 = 0.f, sum1 = 0.f;
        #pragma unroll
        for (int ni = 0; ni < 8; ni++) {
            const float p0 = __expf(sacc[ni][0] - mn0);
            const float p1 = __expf(sacc[ni][1] - mn0);
            const float p2 = __expf(sacc[ni][2] - mn1);
            const float p3 = __expf(sacc[ni][3] - mn1);
            sum0 += p0 + p1; sum1 += p2 + p3;
            __half2 h0 = __floats2half2_rn(p0, p1);
            __half2 h1 = __floats2half2_rn(p2, p3);
            pa[ni][0] = *(uint32_t*)&h0;
            pa[ni][1] = *(uint32_t*)&h1;
        }
        sum0 += __shfl_xor_sync(0xffffffffu, sum0, 1);
        sum0 += __shfl_xor_sync(0xffffffffu, sum0, 2);
        sum1 += __shfl_xor_sync(0xffffffffu, sum1, 1);
        sum1 += __shfl_xor_sync(0xffffffffu, sum1, 2);
        l0 = l0 * al0 + sum0;
        l1 = l1 * al1 + sum1;

        #pragma unroll
        for (int ni = 0; ni < 8; ni++) {
            oacc[ni][0] *= al0; oacc[ni][1] *= al0;
            oacc[ni][2] *= al1; oacc[ni][3] *= al1;
        }

        #pragma unroll
        for (int kk = 0; kk < 4; kk++) {
            uint32_t bv[8][2];
            #pragma unroll
            for (int bb = 0; bb < 4; bb++) {
                const int key = 16 * kk + kV;
                LDSM4T(bv[2*bb][0], bv[2*bb][1], bv[2*bb+1][0], bv[2*bb+1][1],
                       vbuf + key * 128 + (((2 * bb + cV) ^ swz) << 4));
            }
            uint32_t ap[4] = { pa[2*kk][0], pa[2*kk][1], pa[2*kk+1][0], pa[2*kk+1][1] };
            #pragma unroll
            for (int ni = 0; ni < 8; ni++)
                mma16(oacc[ni], ap, bv[ni]);
        }

        cur = (cur == 2) ? 0 : cur + 1;
    }
    #undef ISSUE_KV

    const float inv0 = 1.f / l0;
    const float inv1 = 1.f / l1;
    const size_t row0 = obase + (size_t)(q0 + wid * 16 + g) * D_MODEL;
    const size_t row1 = row0 + (size_t)8 * D_MODEL;
    #pragma unroll
    for (int ni = 0; ni < 8; ni++) {
        const int c = ni * 8 + 2 * t;
        __half2 h0 = __floats2half2_rn(oacc[ni][0] * inv0, oacc[ni][1] * inv0);
        __half2 h1 = __floats2half2_rn(oacc[ni][2] * inv1, oacc[ni][3] * inv1);
        *(uint32_t*)&O[row0 + c] = *(uint32_t*)&h0;
        *(uint32_t*)&O[row1 + c] = *(uint32_t*)&h1;
    }
}

// ---------------- launch: four batch chains on main + 3 reused streams ----------------
extern "C" void kernel_launch(void* const* d_in, const int* in_sizes, int n_in,
                              void* d_out, int out_size)
{
    const float* x    = (const float*)d_in[0];
    const float* ln1g = (const float*)d_in[1];
    const float* ln1b = (const float*)d_in[2];
    const float* ln2g = (const float*)d_in[3];
    const float* ln2b = (const float*)d_in[4];
    const float* Wq = (const float*)d_in[5];
    const float* bq = (const float*)d_in[6];
    const float* Wk = (const float*)d_in[7];
    const float* bk = (const float*)d_in[8];
    const float* Wv = (const float*)d_in[9];
    const float* bv = (const float*)d_in[10];
    const float* Wo = (const float*)d_in[11];
    const float* bo = (const float*)d_in[12];
    const float* W1 = (const float*)d_in[13];
    const float* b1 = (const float*)d_in[14];
    const float* W2 = (const float*)d_in[15];
    const float* b2 = (const float*)d_in[16];
    float* out = (float*)d_out;

    __half *xnh, *qkvh, *ctxh, *ffh, *wqkvh, *woh, *w1h, *w2h;
    float *x1, *bqkv;
    cudaGetSymbolAddress((void**)&xnh,   g_xnh);
    cudaGetSymbolAddress((void**)&qkvh,  g_qkvh);
    cudaGetSymbolAddress((void**)&ctxh,  g_ctxh);
    cudaGetSymbolAddress((void**)&x1,    g_x1);
    cudaGetSymbolAddress((void**)&ffh,   g_ffh);
    cudaGetSymbolAddress((void**)&wqkvh, g_wqkvh);
    cudaGetSymbolAddress((void**)&woh,   g_woh);
    cudaGetSymbolAddress((void**)&w1h,   g_w1h);
    cudaGetSymbolAddress((void**)&w2h,   g_w2h);
    cudaGetSymbolAddress((void**)&bqkv,  g_bqkv);

    cudaFuncSetAttribute(attn_h, cudaFuncAttributeMaxDynamicSharedMemorySize, ATT_SMEM);
    cudaFuncSetAttribute(gemm_h<false,false,true>,  cudaFuncAttributeMaxDynamicSharedMemorySize, GSM_TOTAL);
    cudaFuncSetAttribute(gemm_h<false,true,false>,  cudaFuncAttributeMaxDynamicSharedMemorySize, GSM_TOTAL);
    cudaFuncSetAttribute(gemm_h<true,false,true>,   cudaFuncAttributeMaxDynamicSharedMemorySize, GSM_TOTAL);

    // 3 created streams total (fewer than the passing R15's 4)
    cudaStream_t st[3];
    for (int i = 0; i < 3; i++) cudaStreamCreateWithFlags(&st[i], cudaStreamNonBlocking);
    cudaEvent_t eFork, eQkv, eWo, eW12, eDone[3];
    cudaEventCreateWithFlags(&eFork, cudaEventDisableTiming);
    cudaEventCreateWithFlags(&eQkv,  cudaEventDisableTiming);
    cudaEventCreateWithFlags(&eWo,   cudaEventDisableTiming);
    cudaEventCreateWithFlags(&eW12,  cudaEventDisableTiming);
    for (int i = 0; i < 3; i++) cudaEventCreateWithFlags(&eDone[i], cudaEventDisableTiming);

    cudaEventRecord(eFork, 0);
    for (int i = 0; i < 3; i++) cudaStreamWaitEvent(st[i], eFork, 0);

    // converts, one per side stream (each stream then runs a batch chain)
    convert_qkv<<<512, 256, 0, st[0]>>>(Wq, Wk, Wv, bqkv, bq, bk, bv, wqkvh);
    cudaEventRecord(eQkv, st[0]);
    convert_h<<<(D_MODEL*D_MODEL)/4096, 256, 0, st[1]>>>(Wo, woh);
    cudaEventRecord(eWo, st[1]);
    convert_h<<<(D_MODEL*D_FF)/4096, 256, 0, st[2]>>>(W1, w1h);
    convert_h<<<(D_FF*D_MODEL)/4096, 256, 0, st[2]>>>(W2, w2h);
    cudaEventRecord(eW12, st[2]);

    // chain macro: stream S, token offset R; WQ/WO/W12 = whether the stream
    // still needs to wait on that convert event (its own stream's convert is
    // already ordered by stream order).
    #define CHAIN(S, R, NQ, NO, N12) do { \
        const size_t rD  = (size_t)(R) * D_MODEL; \
        const size_t r3D = (size_t)(R) * 3 * D_MODEL; \
        const size_t rF  = (size_t)(R) * D_FF; \
        ln_kernel<<<QTOK/8, 256, 0, (S)>>>(x + rD, ln1g, ln1b, xnh + rD); \
        if (NQ) cudaStreamWaitEvent((S), eQkv, 0); \
        gemm_h<false,false,true><<<dim3(3*D_MODEL/128, QTOK/128), 128, GSM_TOTAL, (S)>>>( \
            xnh + rD, wqkvh, bqkv, nullptr, nullptr, qkvh + r3D, QTOK, 3*D_MODEL, D_MODEL); \
        attn_h<<<dim3(SEQ/128, NHEAD), 256, ATT_SMEM, (S)>>>( \
            qkvh + r3D, qkvh + r3D + D_MODEL, qkvh + r3D + 2*D_MODEL, ctxh + rD, 3*D_MODEL); \
        if (NO) cudaStreamWaitEvent((S), eWo, 0); \
        gemm_h<false,true,false><<<dim3(D_MODEL/128, QTOK/128), 128, GSM_TOTAL, (S)>>>( \
            ctxh + rD, woh, bo, x + rD, x1 + rD, nullptr, QTOK, D_MODEL, D_MODEL); \
        ln_kernel<<<QTOK/8, 256, 0, (S)>>>(x1 + rD, ln2g, ln2b, xnh + rD); \
        if (N12) cudaStreamWaitEvent((S), eW12, 0); \
        gemm_h<true,false,true><<<dim3(D_FF/128, QTOK/128), 128, GSM_TOTAL, (S)>>>( \
            xnh + rD, w1h, b1, nullptr, nullptr, ffh + rF, QTOK, D_FF, D_MODEL); \
        gemm_h<false,true,false><<<dim3(D_MODEL/128, QTOK/128), 128, GSM_TOTAL, (S)>>>( \
            ffh + rF, w2h, b2, x1 + rD, out + rD, nullptr, QTOK, D_MODEL, D_FF); \
    } while (0)

    CHAIN(st[0], 1 * QTOK, 0, 1, 1);   // own stream did qkv convert
    CHAIN(st[1], 2 * QTOK, 1, 0, 1);   // own stream did Wo convert
    CHAIN(st[2], 3 * QTOK, 1, 1, 0);   // own stream did W1/W2 converts
    {
        // main stream chain: must wait on all three converts
        cudaStreamWaitEvent(0, eQkv, 0);   // before GEMM2 (placed early; LN first)
        CHAIN((cudaStream_t)0, 0, 1, 1, 1);
    }
    #undef CHAIN

    for (int i = 0; i < 3; i++) {
        cudaEventRecord(eDone[i], st[i]);
        cudaStreamWaitEvent(0, eDone[i], 0);
    }

    cudaEventDestroy(eFork);
    cudaEventDestroy(eQkv);
    cudaEventDestroy(eWo);
    cudaEventDestroy(eW12);
    for (int i = 0; i < 3; i++) cudaEventDestroy(eDone[i]);
    for (int i = 0; i < 3; i++) cudaStreamDestroy(st[i]);
}